// round 2
// baseline (speedup 1.0000x reference)
#include <cuda_runtime.h>
#include <math.h>

#define NN 50000
#define NE 800000

// ---------------- scratch (static device globals; no allocation) ----------------
__device__ int   g_is64;
__device__ int   g_deg[NN];
__device__ int   g_off[NN + 1];
__device__ int   g_cur[NN];
__device__ int   g_csr[NE];
__device__ float g_amp[NN];
__device__ float g_att[NN];
__device__ float g_P[NN * 128];
__device__ float g_Q[NN * 128];
__device__ float g_agg[NN * 384];
__device__ float g_h1[NN * 128];
__device__ float g_h2[NN * 128];

// ---------------- index-width detection (int32 vs int64 indices) ----------------
__global__ void detect_kernel(const void* dst, int e, int n) {
    // One block. Interpret as int64: if any of the first K entries is out of
    // [0, n), the buffer is int32 (two packed 32-bit values look huge).
    __shared__ int bad;
    if (threadIdx.x == 0) bad = 0;
    __syncthreads();
    int k = e < 1024 ? e : 1024;
    const long long* p = (const long long*)dst;
    for (int i = threadIdx.x; i < k; i += blockDim.x) {
        long long v = p[i];
        if (v < 0 || v >= (long long)n) atomicExch(&bad, 1);
    }
    __syncthreads();
    if (threadIdx.x == 0) g_is64 = bad ? 0 : 1;
}

__device__ __forceinline__ int load_idx(const void* p, int i) {
    if (g_is64) return (int)((const long long*)p)[i];
    return ((const int*)p)[i];
}

// ---------------- CSR build ----------------
__global__ void zero_deg(int n) {
    int i = blockIdx.x * blockDim.x + threadIdx.x;
    if (i < n) g_deg[i] = 0;
}

__global__ void hist_kernel(const void* __restrict__ dst, int e) {
    int i = blockIdx.x * blockDim.x + threadIdx.x;
    if (i < e) atomicAdd(&g_deg[load_idx(dst, i)], 1);
}

__global__ void scan_kernel(int n) {
    // single block, 1024 threads: chunked Hillis-Steele inclusive scan
    __shared__ int temp[1024];
    __shared__ int carry;
    int tid = threadIdx.x;
    if (tid == 0) carry = 0;
    __syncthreads();
    for (int base = 0; base < n; base += 1024) {
        int i = base + tid;
        int v = (i < n) ? g_deg[i] : 0;
        temp[tid] = v;
        __syncthreads();
        #pragma unroll
        for (int off = 1; off < 1024; off <<= 1) {
            int t = (tid >= off) ? temp[tid - off] : 0;
            __syncthreads();
            temp[tid] += t;
            __syncthreads();
        }
        int incl = temp[tid] + carry;
        if (i < n) {
            int excl = incl - v;
            g_off[i] = excl;
            g_cur[i] = excl;
            float d  = (float)v;
            float ld = logf(d + 1.0f);
            g_amp[i] = ld * (1.0f / 3.0f);
            g_att[i] = 3.0f / fmaxf(ld, 1e-6f);
        }
        __syncthreads();
        if (tid == 0) carry += temp[1023];
        __syncthreads();
    }
    if (tid == 0) g_off[n] = carry;
}

__global__ void scatter_kernel(const void* __restrict__ src,
                               const void* __restrict__ dst, int e) {
    int i = blockIdx.x * blockDim.x + threadIdx.x;
    if (i < e) {
        int d   = load_idx(dst, i);
        int pos = atomicAdd(&g_cur[d], 1);
        g_csr[pos] = load_idx(src, i);
    }
}

// ---------------- input selection helper ----------------
template <int SEL>
__device__ __forceinline__ const float* sel_in(const float* a) {
    if constexpr (SEL == 1) return g_h1;
    else if constexpr (SEL == 2) return g_h2;
    else return a;
}

// ---------------- P/Q GEMM: C[MxN=128] = A[Mx128] @ B[128x128] (+bias on Q) ----------------
template <int INSEL, bool QSIDE>
__global__ __launch_bounds__(256) void sgemm_pq(const float* __restrict__ hin,
                                                const float* __restrict__ Mw,
                                                const float* __restrict__ Mb,
                                                int M) {
    const float* A = sel_in<INSEL>(hin);
    const float* B = Mw + (QSIDE ? 128 * 128 : 0);
    float* C       = QSIDE ? g_Q : g_P;

    __shared__ float As[16][132];
    __shared__ float Bs[16][128];

    int tid  = threadIdx.x;
    int ty   = tid >> 4, tx = tid & 15;
    int row0 = blockIdx.x * 128;
    float acc[8][8] = {};
    int rA = tid >> 2, cA = (tid & 3) << 2;
    int rB = tid >> 5, cB = (tid & 31) << 2;

    for (int k0 = 0; k0 < 128; k0 += 16) {
        #pragma unroll
        for (int p = 0; p < 2; p++) {
            int gr = row0 + rA + p * 64;
            float4 v = make_float4(0.f, 0.f, 0.f, 0.f);
            if (gr < M) v = *(const float4*)(A + (long)gr * 128 + k0 + cA);
            As[cA + 0][rA + p * 64] = v.x;
            As[cA + 1][rA + p * 64] = v.y;
            As[cA + 2][rA + p * 64] = v.z;
            As[cA + 3][rA + p * 64] = v.w;
        }
        #pragma unroll
        for (int p = 0; p < 2; p++) {
            *(float4*)&Bs[rB + p * 8][cB] =
                *(const float4*)(B + (k0 + rB + p * 8) * 128 + cB);
        }
        __syncthreads();
        #pragma unroll
        for (int kk = 0; kk < 16; kk++) {
            float a[8], b[8];
            #pragma unroll
            for (int m = 0; m < 8; m++) a[m] = As[kk][ty * 8 + m];
            #pragma unroll
            for (int nn = 0; nn < 8; nn++) b[nn] = Bs[kk][tx * 8 + nn];
            #pragma unroll
            for (int m = 0; m < 8; m++)
                #pragma unroll
                for (int nn = 0; nn < 8; nn++)
                    acc[m][nn] = fmaf(a[m], b[nn], acc[m][nn]);
        }
        __syncthreads();
    }
    #pragma unroll
    for (int m = 0; m < 8; m++) {
        int gr = row0 + ty * 8 + m;
        if (gr < M) {
            #pragma unroll
            for (int nn = 0; nn < 8; nn++) {
                int gc  = tx * 8 + nn;
                float v = acc[m][nn];
                if (QSIDE) v += Mb[gc];
                C[(long)gr * 128 + gc] = v;
            }
        }
    }
}

// ---------------- CSR aggregation: warp per node, float4 per lane ----------------
__global__ void agg_kernel(int n) {
    int gw   = (blockIdx.x * blockDim.x + threadIdx.x) >> 5;
    int lane = threadIdx.x & 31;
    if (gw >= n) return;
    int s = g_off[gw], e = g_off[gw + 1];
    int c = lane * 4;
    float4 sum = make_float4(0.f, 0.f, 0.f, 0.f);
    float4 mn  = make_float4(1e30f, 1e30f, 1e30f, 1e30f);
    float4 mx  = make_float4(-1e30f, -1e30f, -1e30f, -1e30f);
    for (int i = s; i < e; i++) {
        int r    = g_csr[i];
        float4 v = *(const float4*)&g_P[(long)r * 128 + c];
        sum.x += v.x; sum.y += v.y; sum.z += v.z; sum.w += v.w;
        mn.x = fminf(mn.x, v.x); mn.y = fminf(mn.y, v.y);
        mn.z = fminf(mn.z, v.z); mn.w = fminf(mn.w, v.w);
        mx.x = fmaxf(mx.x, v.x); mx.y = fmaxf(mx.y, v.y);
        mx.z = fmaxf(mx.z, v.z); mx.w = fmaxf(mx.w, v.w);
    }
    float4 q = *(const float4*)&g_Q[(long)gw * 128 + c];
    float4 me, on, ox;
    int d = e - s;
    if (d > 0) {
        float inv = 1.0f / (float)d;
        me.x = sum.x * inv + q.x; me.y = sum.y * inv + q.y;
        me.z = sum.z * inv + q.z; me.w = sum.w * inv + q.w;
        on.x = mn.x + q.x; on.y = mn.y + q.y; on.z = mn.z + q.z; on.w = mn.w + q.w;
        ox.x = mx.x + q.x; ox.y = mx.y + q.y; ox.z = mx.z + q.z; ox.w = mx.w + q.w;
    } else {
        me = make_float4(0.f, 0.f, 0.f, 0.f);
        on = me; ox = me;
    }
    *(float4*)&g_agg[(long)gw * 384 + c]       = me;
    *(float4*)&g_agg[(long)gw * 384 + 128 + c] = on;
    *(float4*)&g_agg[(long)gw * 384 + 256 + c] = ox;
}

// ---------------- fused update GEMM ----------------
// C[M x BN] = [ h | agg | agg*amp | agg*att ] (M x 1280) @ Uw (1280 x BN) + Ub
// A is synthesized in the tile loader (region select + per-row scale).
template <int INSEL, int OUTSEL, int BN, int TN, bool RELU>
__global__ __launch_bounds__(256) void sgemm_update(const float* __restrict__ hin,
                                                    const float* __restrict__ Uw,
                                                    const float* __restrict__ Ub,
                                                    float* __restrict__ outp,
                                                    int M) {
    const float* H = sel_in<INSEL>(hin);
    float* C;
    if constexpr (OUTSEL == 1) C = g_h1;
    else if constexpr (OUTSEL == 2) C = g_h2;
    else C = outp;

    constexpr int TM = 8, BK = 16, BM = 128;
    constexpr int TXN = BN / TN;
    __shared__ float As[BK][BM + 4];
    __shared__ float Bs[BK][BN];

    int tid  = threadIdx.x;
    int ty   = tid / TXN, tx = tid % TXN;
    int row0 = blockIdx.x * BM;
    float acc[TM][TN] = {};
    int rA = tid >> 2, cA = (tid & 3) << 2;
    constexpr int QPR = BN / 4;     // float4 slots per B row
    constexpr int RPP = 256 / QPR;  // B rows loaded per pass
    int rB = tid / QPR, cB = (tid % QPR) * 4;

    for (int kt = 0; kt < 80; kt++) {
        int k0 = kt * 16;
        #pragma unroll
        for (int p = 0; p < 2; p++) {
            int gr = row0 + rA + p * 64;
            float4 v = make_float4(0.f, 0.f, 0.f, 0.f);
            if (gr < M) {
                if (k0 < 128) {
                    v = *(const float4*)(H + (long)gr * 128 + k0 + cA);
                } else {
                    int koff; float s;
                    if (k0 < 512)      { koff = k0 - 128; s = 1.0f; }
                    else if (k0 < 896) { koff = k0 - 512; s = g_amp[gr]; }
                    else               { koff = k0 - 896; s = g_att[gr]; }
                    v = *(const float4*)(g_agg + (long)gr * 384 + koff + cA);
                    v.x *= s; v.y *= s; v.z *= s; v.w *= s;
                }
            }
            As[cA + 0][rA + p * 64] = v.x;
            As[cA + 1][rA + p * 64] = v.y;
            As[cA + 2][rA + p * 64] = v.z;
            As[cA + 3][rA + p * 64] = v.w;
        }
        #pragma unroll
        for (int p = 0; p < BK / RPP; p++) {
            *(float4*)&Bs[rB + p * RPP][cB] =
                *(const float4*)(Uw + (long)(k0 + rB + p * RPP) * BN + cB);
        }
        __syncthreads();
        #pragma unroll
        for (int kk = 0; kk < BK; kk++) {
            float a[TM], b[TN];
            #pragma unroll
            for (int m = 0; m < TM; m++) a[m] = As[kk][ty * TM + m];
            #pragma unroll
            for (int nn = 0; nn < TN; nn++) b[nn] = Bs[kk][tx * TN + nn];
            #pragma unroll
            for (int m = 0; m < TM; m++)
                #pragma unroll
                for (int nn = 0; nn < TN; nn++)
                    acc[m][nn] = fmaf(a[m], b[nn], acc[m][nn]);
        }
        __syncthreads();
    }
    #pragma unroll
    for (int m = 0; m < TM; m++) {
        int gr = row0 + ty * TM + m;
        if (gr < M) {
            #pragma unroll
            for (int nn = 0; nn < TN; nn++) {
                int gc  = tx * TN + nn;
                float v = acc[m][nn] + Ub[gc];
                if (RELU) v = fmaxf(v, 0.0f);
                C[(long)gr * BN + gc] = v;
            }
        }
    }
}

// ---------------- host launcher ----------------
extern "C" void kernel_launch(void* const* d_in, const int* in_sizes, int n_in,
                              void* d_out, int out_size) {
    const float* x   = (const float*)d_in[0];
    const void*  src = d_in[1];
    const void*  dst = d_in[2];
    const float* M0w = (const float*)d_in[3];
    const float* M0b = (const float*)d_in[4];
    const float* U0w = (const float*)d_in[5];
    const float* U0b = (const float*)d_in[6];
    const float* M1w = (const float*)d_in[7];
    const float* M1b = (const float*)d_in[8];
    const float* U1w = (const float*)d_in[9];
    const float* U1b = (const float*)d_in[10];
    const float* M2w = (const float*)d_in[11];
    const float* M2b = (const float*)d_in[12];
    const float* U2w = (const float*)d_in[13];
    const float* U2b = (const float*)d_in[14];

    int n = in_sizes[0] / 128;
    int e = in_sizes[1];
    if (n > NN) n = NN;
    if (e > NE) e = NE;

    int gE = (e + 255) / 256;
    int gN = (n + 255) / 256;
    int gM = (n + 127) / 128;
    int gA = (n * 32 + 255) / 256;

    // CSR build + node scalars
    detect_kernel<<<1, 256>>>(dst, e, n);
    zero_deg<<<gN, 256>>>(n);
    hist_kernel<<<gE, 256>>>(dst, e);
    scan_kernel<<<1, 1024>>>(n);
    scatter_kernel<<<gE, 256>>>(src, dst, e);

    // layer 0: in = x, out = g_h1
    sgemm_pq<0, false><<<gM, 256>>>(x, M0w, nullptr, n);
    sgemm_pq<0, true ><<<gM, 256>>>(x, M0w, M0b, n);
    agg_kernel<<<gA, 256>>>(n);
    sgemm_update<0, 1, 128, 8, true><<<gM, 256>>>(x, U0w, U0b, nullptr, n);

    // layer 1: in = g_h1, out = g_h2
    sgemm_pq<1, false><<<gM, 256>>>(nullptr, M1w, nullptr, n);
    sgemm_pq<1, true ><<<gM, 256>>>(nullptr, M1w, M1b, n);
    agg_kernel<<<gA, 256>>>(n);
    sgemm_update<1, 2, 128, 8, true><<<gM, 256>>>(nullptr, U1w, U1b, nullptr, n);

    // layer 2: in = g_h2, out = d_out (N=64, no relu)
    sgemm_pq<2, false><<<gM, 256>>>(nullptr, M2w, nullptr, n);
    sgemm_pq<2, true ><<<gM, 256>>>(nullptr, M2w, M2b, n);
    agg_kernel<<<gA, 256>>>(n);
    sgemm_update<2, 0, 64, 4, false><<<gM, 256>>>(nullptr, U2w, U2b,
                                                  (float*)d_out, n);
}

// round 3
// speedup vs baseline: 1.0023x; 1.0023x over previous
#include <cuda_runtime.h>
#include <math.h>

#define NN 50000
#define NE 800000

// ---------------- scratch (static device globals; no allocation) ----------------
__device__ int   g_is64;
__device__ int   g_deg[NN];
__device__ int   g_off[NN + 1];
__device__ int   g_cur[NN];
__device__ int   g_csr[NE];
__device__ float g_amp[NN];
__device__ float g_att[NN];
__device__ float g_P[NN * 128];
__device__ float g_Q[NN * 128];
__device__ float g_agg[NN * 384];
__device__ float g_h1[NN * 128];
__device__ float g_h2[NN * 128];

// ---------------- index-width detection (int32 vs int64 indices) ----------------
__global__ void detect_kernel(const void* dst, int e, int n) {
    // One block. Interpret as int64: if any of the first K entries is out of
    // [0, n), the buffer is int32 (two packed 32-bit values look huge).
    __shared__ int bad;
    if (threadIdx.x == 0) bad = 0;
    __syncthreads();
    int k = e < 1024 ? e : 1024;
    const long long* p = (const long long*)dst;
    for (int i = threadIdx.x; i < k; i += blockDim.x) {
        long long v = p[i];
        if (v < 0 || v >= (long long)n) atomicExch(&bad, 1);
    }
    __syncthreads();
    if (threadIdx.x == 0) g_is64 = bad ? 0 : 1;
}

__device__ __forceinline__ int load_idx(const void* p, int i) {
    if (g_is64) return (int)((const long long*)p)[i];
    return ((const int*)p)[i];
}

// ---------------- CSR build ----------------
__global__ void zero_deg(int n) {
    int i = blockIdx.x * blockDim.x + threadIdx.x;
    if (i < n) g_deg[i] = 0;
}

__global__ void hist_kernel(const void* __restrict__ dst, int e) {
    int i = blockIdx.x * blockDim.x + threadIdx.x;
    if (i < e) atomicAdd(&g_deg[load_idx(dst, i)], 1);
}

__global__ void scan_kernel(int n) {
    // single block, 1024 threads: chunked Hillis-Steele inclusive scan
    __shared__ int temp[1024];
    __shared__ int carry;
    int tid = threadIdx.x;
    if (tid == 0) carry = 0;
    __syncthreads();
    for (int base = 0; base < n; base += 1024) {
        int i = base + tid;
        int v = (i < n) ? g_deg[i] : 0;
        temp[tid] = v;
        __syncthreads();
        #pragma unroll
        for (int off = 1; off < 1024; off <<= 1) {
            int t = (tid >= off) ? temp[tid - off] : 0;
            __syncthreads();
            temp[tid] += t;
            __syncthreads();
        }
        int incl = temp[tid] + carry;
        if (i < n) {
            int excl = incl - v;
            g_off[i] = excl;
            g_cur[i] = excl;
            float d  = (float)v;
            float ld = logf(d + 1.0f);
            g_amp[i] = ld * (1.0f / 3.0f);
            g_att[i] = 3.0f / fmaxf(ld, 1e-6f);
        }
        __syncthreads();
        if (tid == 0) carry += temp[1023];
        __syncthreads();
    }
    if (tid == 0) g_off[n] = carry;
}

__global__ void scatter_kernel(const void* __restrict__ src,
                               const void* __restrict__ dst, int e) {
    int i = blockIdx.x * blockDim.x + threadIdx.x;
    if (i < e) {
        int d   = load_idx(dst, i);
        int pos = atomicAdd(&g_cur[d], 1);
        g_csr[pos] = load_idx(src, i);
    }
}

// ---------------- input selection helper ----------------
template <int SEL>
__device__ __forceinline__ const float* sel_in(const float* a) {
    if constexpr (SEL == 1) return g_h1;
    else if constexpr (SEL == 2) return g_h2;
    else return a;
}

// ---------------- P/Q GEMM: C[MxN=128] = A[Mx128] @ B[128x128] (+bias on Q) ----------------
template <int INSEL, bool QSIDE>
__global__ __launch_bounds__(256) void sgemm_pq(const float* __restrict__ hin,
                                                const float* __restrict__ Mw,
                                                const float* __restrict__ Mb,
                                                int M) {
    const float* A = sel_in<INSEL>(hin);
    const float* B = Mw + (QSIDE ? 128 * 128 : 0);
    float* C       = QSIDE ? g_Q : g_P;

    __shared__ float As[16][132];
    __shared__ float Bs[16][128];

    int tid  = threadIdx.x;
    int ty   = tid >> 4, tx = tid & 15;
    int row0 = blockIdx.x * 128;
    float acc[8][8] = {};
    int rA = tid >> 2, cA = (tid & 3) << 2;
    int rB = tid >> 5, cB = (tid & 31) << 2;

    for (int k0 = 0; k0 < 128; k0 += 16) {
        #pragma unroll
        for (int p = 0; p < 2; p++) {
            int gr = row0 + rA + p * 64;
            float4 v = make_float4(0.f, 0.f, 0.f, 0.f);
            if (gr < M) v = *(const float4*)(A + (long)gr * 128 + k0 + cA);
            As[cA + 0][rA + p * 64] = v.x;
            As[cA + 1][rA + p * 64] = v.y;
            As[cA + 2][rA + p * 64] = v.z;
            As[cA + 3][rA + p * 64] = v.w;
        }
        #pragma unroll
        for (int p = 0; p < 2; p++) {
            *(float4*)&Bs[rB + p * 8][cB] =
                *(const float4*)(B + (k0 + rB + p * 8) * 128 + cB);
        }
        __syncthreads();
        #pragma unroll
        for (int kk = 0; kk < 16; kk++) {
            float a[8], b[8];
            #pragma unroll
            for (int m = 0; m < 8; m++) a[m] = As[kk][ty * 8 + m];
            #pragma unroll
            for (int nn = 0; nn < 8; nn++) b[nn] = Bs[kk][tx * 8 + nn];
            #pragma unroll
            for (int m = 0; m < 8; m++)
                #pragma unroll
                for (int nn = 0; nn < 8; nn++)
                    acc[m][nn] = fmaf(a[m], b[nn], acc[m][nn]);
        }
        __syncthreads();
    }
    #pragma unroll
    for (int m = 0; m < 8; m++) {
        int gr = row0 + ty * 8 + m;
        if (gr < M) {
            #pragma unroll
            for (int nn = 0; nn < 8; nn++) {
                int gc  = tx * 8 + nn;
                float v = acc[m][nn];
                if (QSIDE) v += Mb[gc];
                C[(long)gr * 128 + gc] = v;
            }
        }
    }
}

// ---------------- CSR aggregation: warp per node, float4 per lane ----------------
__global__ void agg_kernel(int n) {
    int gw   = (blockIdx.x * blockDim.x + threadIdx.x) >> 5;
    int lane = threadIdx.x & 31;
    if (gw >= n) return;
    int s = g_off[gw], e = g_off[gw + 1];
    int c = lane * 4;
    float4 sum = make_float4(0.f, 0.f, 0.f, 0.f);
    float4 mn  = make_float4(1e30f, 1e30f, 1e30f, 1e30f);
    float4 mx  = make_float4(-1e30f, -1e30f, -1e30f, -1e30f);
    for (int i = s; i < e; i++) {
        int r    = g_csr[i];
        float4 v = *(const float4*)&g_P[(long)r * 128 + c];
        sum.x += v.x; sum.y += v.y; sum.z += v.z; sum.w += v.w;
        mn.x = fminf(mn.x, v.x); mn.y = fminf(mn.y, v.y);
        mn.z = fminf(mn.z, v.z); mn.w = fminf(mn.w, v.w);
        mx.x = fmaxf(mx.x, v.x); mx.y = fmaxf(mx.y, v.y);
        mx.z = fmaxf(mx.z, v.z); mx.w = fmaxf(mx.w, v.w);
    }
    float4 q = *(const float4*)&g_Q[(long)gw * 128 + c];
    float4 me, on, ox;
    int d = e - s;
    if (d > 0) {
        float inv = 1.0f / (float)d;
        me.x = sum.x * inv + q.x; me.y = sum.y * inv + q.y;
        me.z = sum.z * inv + q.z; me.w = sum.w * inv + q.w;
        on.x = mn.x + q.x; on.y = mn.y + q.y; on.z = mn.z + q.z; on.w = mn.w + q.w;
        ox.x = mx.x + q.x; ox.y = mx.y + q.y; ox.z = mx.z + q.z; ox.w = mx.w + q.w;
    } else {
        me = make_float4(0.f, 0.f, 0.f, 0.f);
        on = me; ox = me;
    }
    *(float4*)&g_agg[(long)gw * 384 + c]       = me;
    *(float4*)&g_agg[(long)gw * 384 + 128 + c] = on;
    *(float4*)&g_agg[(long)gw * 384 + 256 + c] = ox;
}

// ---------------- fused update GEMM ----------------
// C[M x BN] = [ h | agg | agg*amp | agg*att ] (M x 1280) @ Uw (1280 x BN) + Ub
// A is synthesized in the tile loader (region select + per-row scale).
template <int INSEL, int OUTSEL, int BN, int TN, bool RELU>
__global__ __launch_bounds__(256) void sgemm_update(const float* __restrict__ hin,
                                                    const float* __restrict__ Uw,
                                                    const float* __restrict__ Ub,
                                                    float* __restrict__ outp,
                                                    int M) {
    const float* H = sel_in<INSEL>(hin);
    float* C;
    if constexpr (OUTSEL == 1) C = g_h1;
    else if constexpr (OUTSEL == 2) C = g_h2;
    else C = outp;

    constexpr int TM = 8, BK = 16, BM = 128;
    constexpr int TXN = BN / TN;
    __shared__ float As[BK][BM + 4];
    __shared__ float Bs[BK][BN];

    int tid  = threadIdx.x;
    int ty   = tid / TXN, tx = tid % TXN;
    int row0 = blockIdx.x * BM;
    float acc[TM][TN] = {};
    int rA = tid >> 2, cA = (tid & 3) << 2;
    constexpr int QPR = BN / 4;     // float4 slots per B row
    constexpr int RPP = 256 / QPR;  // B rows loaded per pass
    int rB = tid / QPR, cB = (tid % QPR) * 4;

    for (int kt = 0; kt < 80; kt++) {
        int k0 = kt * 16;
        #pragma unroll
        for (int p = 0; p < 2; p++) {
            int gr = row0 + rA + p * 64;
            float4 v = make_float4(0.f, 0.f, 0.f, 0.f);
            if (gr < M) {
                if (k0 < 128) {
                    v = *(const float4*)(H + (long)gr * 128 + k0 + cA);
                } else {
                    int koff; float s;
                    if (k0 < 512)      { koff = k0 - 128; s = 1.0f; }
                    else if (k0 < 896) { koff = k0 - 512; s = g_amp[gr]; }
                    else               { koff = k0 - 896; s = g_att[gr]; }
                    v = *(const float4*)(g_agg + (long)gr * 384 + koff + cA);
                    v.x *= s; v.y *= s; v.z *= s; v.w *= s;
                }
            }
            As[cA + 0][rA + p * 64] = v.x;
            As[cA + 1][rA + p * 64] = v.y;
            As[cA + 2][rA + p * 64] = v.z;
            As[cA + 3][rA + p * 64] = v.w;
        }
        #pragma unroll
        for (int p = 0; p < BK / RPP; p++) {
            *(float4*)&Bs[rB + p * RPP][cB] =
                *(const float4*)(Uw + (long)(k0 + rB + p * RPP) * BN + cB);
        }
        __syncthreads();
        #pragma unroll
        for (int kk = 0; kk < BK; kk++) {
            float a[TM], b[TN];
            #pragma unroll
            for (int m = 0; m < TM; m++) a[m] = As[kk][ty * TM + m];
            #pragma unroll
            for (int nn = 0; nn < TN; nn++) b[nn] = Bs[kk][tx * TN + nn];
            #pragma unroll
            for (int m = 0; m < TM; m++)
                #pragma unroll
                for (int nn = 0; nn < TN; nn++)
                    acc[m][nn] = fmaf(a[m], b[nn], acc[m][nn]);
        }
        __syncthreads();
    }
    #pragma unroll
    for (int m = 0; m < TM; m++) {
        int gr = row0 + ty * TM + m;
        if (gr < M) {
            #pragma unroll
            for (int nn = 0; nn < TN; nn++) {
                int gc  = tx * TN + nn;
                float v = acc[m][nn] + Ub[gc];
                if (RELU) v = fmaxf(v, 0.0f);
                C[(long)gr * BN + gc] = v;
            }
        }
    }
}

// ---------------- host launcher ----------------
extern "C" void kernel_launch(void* const* d_in, const int* in_sizes, int n_in,
                              void* d_out, int out_size) {
    const float* x   = (const float*)d_in[0];
    const void*  src = d_in[1];
    const void*  dst = d_in[2];
    const float* M0w = (const float*)d_in[3];
    const float* M0b = (const float*)d_in[4];
    const float* U0w = (const float*)d_in[5];
    const float* U0b = (const float*)d_in[6];
    const float* M1w = (const float*)d_in[7];
    const float* M1b = (const float*)d_in[8];
    const float* U1w = (const float*)d_in[9];
    const float* U1b = (const float*)d_in[10];
    const float* M2w = (const float*)d_in[11];
    const float* M2b = (const float*)d_in[12];
    const float* U2w = (const float*)d_in[13];
    const float* U2b = (const float*)d_in[14];

    int n = in_sizes[0] / 128;
    int e = in_sizes[1];
    if (n > NN) n = NN;
    if (e > NE) e = NE;

    int gE = (e + 255) / 256;
    int gN = (n + 255) / 256;
    int gM = (n + 127) / 128;
    int gA = (n * 32 + 255) / 256;

    // CSR build + node scalars
    detect_kernel<<<1, 256>>>(dst, e, n);
    zero_deg<<<gN, 256>>>(n);
    hist_kernel<<<gE, 256>>>(dst, e);
    scan_kernel<<<1, 1024>>>(n);
    scatter_kernel<<<gE, 256>>>(src, dst, e);

    // layer 0: in = x, out = g_h1
    sgemm_pq<0, false><<<gM, 256>>>(x, M0w, nullptr, n);
    sgemm_pq<0, true ><<<gM, 256>>>(x, M0w, M0b, n);
    agg_kernel<<<gA, 256>>>(n);
    sgemm_update<0, 1, 128, 8, true><<<gM, 256>>>(x, U0w, U0b, nullptr, n);

    // layer 1: in = g_h1, out = g_h2
    sgemm_pq<1, false><<<gM, 256>>>(nullptr, M1w, nullptr, n);
    sgemm_pq<1, true ><<<gM, 256>>>(nullptr, M1w, M1b, n);
    agg_kernel<<<gA, 256>>>(n);
    sgemm_update<1, 2, 128, 8, true><<<gM, 256>>>(nullptr, U1w, U1b, nullptr, n);

    // layer 2: in = g_h2, out = d_out (N=64, no relu)
    sgemm_pq<2, false><<<gM, 256>>>(nullptr, M2w, nullptr, n);
    sgemm_pq<2, true ><<<gM, 256>>>(nullptr, M2w, M2b, n);
    agg_kernel<<<gA, 256>>>(n);
    sgemm_update<2, 0, 64, 4, false><<<gM, 256>>>(nullptr, U2w, U2b,
                                                  (float*)d_out, n);
}

// round 7
// speedup vs baseline: 1.7487x; 1.7448x over previous
#include <cuda_runtime.h>
#include <cuda_bf16.h>
#include <cstdint>
#include <math.h>

#define NN 50000
#define NE 800000

// ---------------- scratch (static device globals; no allocation) ----------------
__device__ int   g_is64;
__device__ int   g_deg[NN];
__device__ int   g_off[NN + 1];
__device__ int   g_cur[NN];
__device__ int   g_csr[NE];
__device__ float g_amp[NN];
__device__ float g_att[NN];
__device__ float g_P[NN * 128];
__device__ float g_Q[NN * 128];
__device__ float g_agg[NN * 384];
__device__ float g_h1[NN * 128];
__device__ float g_h2[NN * 128];
// prepacked weights: [N][K] row-major bf16, hi and lo images
__device__ unsigned char g_Bhi[1280 * 128 * 2];
__device__ unsigned char g_Blo[1280 * 128 * 2];

// ---------------- helpers ----------------
__device__ __forceinline__ uint32_t smem_u32(const void* p) {
    uint32_t a;
    asm("{ .reg .u64 t; cvta.to.shared.u64 t, %1; cvt.u32.u64 %0, t; }"
        : "=r"(a) : "l"(p));
    return a;
}
__device__ __forceinline__ void ldsm4(uint32_t* r, uint32_t addr) {
    asm volatile("ldmatrix.sync.aligned.m8n8.x4.shared.b16 {%0,%1,%2,%3}, [%4];"
                 : "=r"(r[0]), "=r"(r[1]), "=r"(r[2]), "=r"(r[3]) : "r"(addr));
}
__device__ __forceinline__ void mma16816(float* c, const uint32_t* a,
                                         uint32_t b0, uint32_t b1) {
    asm volatile("mma.sync.aligned.m16n8k16.row.col.f32.bf16.bf16.f32 "
                 "{%0,%1,%2,%3}, {%4,%5,%6,%7}, {%8,%9}, {%0,%1,%2,%3};"
                 : "+f"(c[0]), "+f"(c[1]), "+f"(c[2]), "+f"(c[3])
                 : "r"(a[0]), "r"(a[1]), "r"(a[2]), "r"(a[3]), "r"(b0), "r"(b1));
}

// 16 fp32 -> bf16 hi/lo (scaled), packed as 2+2 uint4
__device__ __forceinline__ void conv16(const float4* f, float s, uint4* Hv, uint4* Lv) {
    uint32_t hw[8], lw[8];
    #pragma unroll
    for (int q = 0; q < 4; q++) {
        float v[4] = {f[q].x * s, f[q].y * s, f[q].z * s, f[q].w * s};
        uint16_t hb[4], lb[4];
        #pragma unroll
        for (int i = 0; i < 4; i++) {
            __nv_bfloat16 h = __float2bfloat16(v[i]);
            float hf        = __bfloat162float(h);
            __nv_bfloat16 l = __float2bfloat16(v[i] - hf);
            hb[i] = __bfloat16_as_ushort(h);
            lb[i] = __bfloat16_as_ushort(l);
        }
        hw[q * 2 + 0] = (uint32_t)hb[0] | ((uint32_t)hb[1] << 16);
        hw[q * 2 + 1] = (uint32_t)hb[2] | ((uint32_t)hb[3] << 16);
        lw[q * 2 + 0] = (uint32_t)lb[0] | ((uint32_t)lb[1] << 16);
        lw[q * 2 + 1] = (uint32_t)lb[2] | ((uint32_t)lb[3] << 16);
    }
    Hv[0] = make_uint4(hw[0], hw[1], hw[2], hw[3]);
    Hv[1] = make_uint4(hw[4], hw[5], hw[6], hw[7]);
    Lv[0] = make_uint4(lw[0], lw[1], lw[2], lw[3]);
    Lv[1] = make_uint4(lw[4], lw[5], lw[6], lw[7]);
}

// ---------------- index-width detection ----------------
__global__ void detect_kernel(const void* dst, int e, int n) {
    __shared__ int bad;
    if (threadIdx.x == 0) bad = 0;
    __syncthreads();
    int k = e < 1024 ? e : 1024;
    const long long* p = (const long long*)dst;
    for (int i = threadIdx.x; i < k; i += blockDim.x) {
        long long v = p[i];
        if (v < 0 || v >= (long long)n) atomicExch(&bad, 1);
    }
    __syncthreads();
    if (threadIdx.x == 0) g_is64 = bad ? 0 : 1;
}
__device__ __forceinline__ int load_idx(const void* p, int i) {
    if (g_is64) return (int)((const long long*)p)[i];
    return ((const int*)p)[i];
}

// ---------------- CSR build ----------------
__global__ void zero_deg(int n) {
    int i = blockIdx.x * blockDim.x + threadIdx.x;
    if (i < n) g_deg[i] = 0;
}
__global__ void hist_kernel(const void* __restrict__ dst, int e) {
    int i = blockIdx.x * blockDim.x + threadIdx.x;
    if (i < e) atomicAdd(&g_deg[load_idx(dst, i)], 1);
}

// one block, 1024 threads: sequential-per-thread + hierarchical scan
__global__ void scan_kernel2(int n) {
    const int T = 1024;
    int tid  = threadIdx.x;
    int C    = (n + T - 1) / T;
    int s    = tid * C;
    int e    = s + C < n ? s + C : n;
    int sum  = 0;
    for (int i = s; i < e; i++) sum += g_deg[i];
    __shared__ int wsum[32];
    int lane = tid & 31, wid = tid >> 5;
    int v = sum;
    #pragma unroll
    for (int o = 1; o < 32; o <<= 1) {
        int t = __shfl_up_sync(0xFFFFFFFFu, v, o);
        if (lane >= o) v += t;
    }
    if (lane == 31) wsum[wid] = v;
    __syncthreads();
    if (wid == 0) {
        int w = wsum[lane];
        #pragma unroll
        for (int o = 1; o < 32; o <<= 1) {
            int t = __shfl_up_sync(0xFFFFFFFFu, w, o);
            if (lane >= o) w += t;
        }
        wsum[lane] = w;
    }
    __syncthreads();
    int excl = v - sum + (wid > 0 ? wsum[wid - 1] : 0);
    int run  = excl;
    for (int i = s; i < e; i++) {
        int d = g_deg[i];
        g_off[i] = run;
        g_cur[i] = run;
        float ld = logf((float)d + 1.0f);
        g_amp[i] = ld * (1.0f / 3.0f);
        g_att[i] = 3.0f / fmaxf(ld, 1e-6f);
        run += d;
    }
    if (s < n && e == n) g_off[n] = run;
}

__global__ void scatter_kernel(const void* __restrict__ src,
                               const void* __restrict__ dst, int e) {
    int i = blockIdx.x * blockDim.x + threadIdx.x;
    if (i < e) {
        int d   = load_idx(dst, i);
        int pos = atomicAdd(&g_cur[d], 1);
        g_csr[pos] = load_idx(src, i);
    }
}

// ---------------- weight prepack: fp32 [K][N] -> bf16 hi/lo [N][K] ----------------
__global__ void prepack_upd2(const float* __restrict__ Uw, int N) {
    int idx = blockIdx.x * blockDim.x + threadIdx.x;
    if (idx >= 1280 * N) return;
    int k = idx / N, n = idx % N;
    float v = Uw[idx];
    __nv_bfloat16 h = __float2bfloat16(v);
    float hf        = __bfloat162float(h);
    __nv_bfloat16 l = __float2bfloat16(v - hf);
    size_t pos = (size_t)n * 1280 + k;
    ((unsigned short*)g_Bhi)[pos] = __bfloat16_as_ushort(h);
    ((unsigned short*)g_Blo)[pos] = __bfloat16_as_ushort(l);
}

// PQ: Mw [256 x 128]; packed B rows: n<128 -> P (Mw top), n>=128 -> Q (Mw bottom)
__global__ void prepack_pq2(const float* __restrict__ Mw) {
    int idx = blockIdx.x * blockDim.x + threadIdx.x;
    if (idx >= 256 * 128) return;
    int n = idx >> 7, k = idx & 127;
    int mat = n >> 7, nn = n & 127;
    float v = Mw[(mat * 128 + k) * 128 + nn];
    __nv_bfloat16 h = __float2bfloat16(v);
    float hf        = __bfloat162float(h);
    __nv_bfloat16 l = __float2bfloat16(v - hf);
    size_t pos = (size_t)n * 128 + k;
    ((unsigned short*)g_Bhi)[pos] = __bfloat16_as_ushort(h);
    ((unsigned short*)g_Blo)[pos] = __bfloat16_as_ushort(l);
}

// ---------------- input selection helper ----------------
template <int SEL>
__device__ __forceinline__ const float* sel_in(const float* a) {
    if constexpr (SEL == 1) return g_h1;
    else if constexpr (SEL == 2) return g_h2;
    else return a;
}

// ---------------- mma.sync update GEMM ----------------
// C[M x BN] = [h|agg|agg*amp|agg*att](M x 1280) @ Uw(1280 x BN) + Ub, bf16x3 fp32-acc
template <int INSEL, int OUTSEL, int BN, bool RELU>
__global__ __launch_bounds__(256, 2) void mma_update(const float* __restrict__ hin,
                                                     const float* __restrict__ Ub,
                                                     float* __restrict__ outp, int M) {
    constexpr int KTOT = 1280, NCH = 40, WNT = BN / 16;  // n-tiles (8 wide) per warp
    __shared__ __align__(16) uint16_t sA[2][128][40];
    __shared__ __align__(16) uint16_t sB[2][BN][40];
    const float* H = sel_in<INSEL>(hin);
    float* C;
    if constexpr (OUTSEL == 1) C = g_h1;
    else if constexpr (OUTSEL == 2) C = g_h2;
    else C = outp;

    int tid = threadIdx.x, lane = tid & 31, wid = tid >> 5;
    int wm = wid & 3, wn = wid >> 2;
    int row0  = blockIdx.x * 128;
    int arow  = tid >> 1, ahalf = (tid & 1) * 16;
    int gr_a  = row0 + arow;
    bool va   = gr_a < M;
    float s_amp = va ? g_amp[gr_a] : 0.f;
    float s_att = va ? g_att[gr_a] : 0.f;

    float acc[2][WNT][4];
    #pragma unroll
    for (int mt = 0; mt < 2; mt++)
        #pragma unroll
        for (int t = 0; t < WNT; t++)
            #pragma unroll
            for (int j = 0; j < 4; j++) acc[mt][t][j] = 0.f;

    uint32_t a_base = smem_u32(&sA[0][0][0]);
    uint32_t b_base = smem_u32(&sB[0][0][0]);
    int lrow = lane & 15, lcol = (lane >> 4) * 8;

    for (int kt = 0; kt < NCH; kt++) {
        int k0 = kt * 32;
        // ---- A fill: region-select + hi/lo split
        const float* bp;
        float s = 1.f;
        if (k0 < 128)      bp = H + (size_t)gr_a * 128 + k0;
        else if (k0 < 512) bp = g_agg + (size_t)gr_a * 384 + (k0 - 128);
        else if (k0 < 896) { bp = g_agg + (size_t)gr_a * 384 + (k0 - 512); s = s_amp; }
        else               { bp = g_agg + (size_t)gr_a * 384 + (k0 - 896); s = s_att; }
        float4 f[4];
        #pragma unroll
        for (int q = 0; q < 4; q++)
            f[q] = va ? *(const float4*)(bp + ahalf + q * 4)
                      : make_float4(0.f, 0.f, 0.f, 0.f);
        uint4 Hv[2], Lv[2];
        conv16(f, s, Hv, Lv);
        *(uint4*)&sA[0][arow][ahalf]     = Hv[0];
        *(uint4*)&sA[0][arow][ahalf + 8] = Hv[1];
        *(uint4*)&sA[1][arow][ahalf]     = Lv[0];
        *(uint4*)&sA[1][arow][ahalf + 8] = Lv[1];
        // ---- B fill from prepacked [N][K] images (BN rows x 32 K-cols x 2 images)
        #pragma unroll
        for (int i = tid; i < BN * 8; i += 256) {
            int img = i >= BN * 4;
            int j   = img ? i - BN * 4 : i;
            int n   = j >> 2, q = j & 3;
            const unsigned char* g = img ? g_Blo : g_Bhi;
            uint4 v = *(const uint4*)(g + ((size_t)n * KTOT + k0 + q * 8) * 2);
            *(uint4*)&sB[img][n][q * 8] = v;
        }
        __syncthreads();
        // ---- mma
        #pragma unroll
        for (int ks = 0; ks < 2; ks++) {
            uint32_t ah[2][4], al[2][4];
            #pragma unroll
            for (int mt = 0; mt < 2; mt++) {
                uint32_t r = a_base + (uint32_t)(((wm * 32 + mt * 16 + lrow) * 40 + ks * 16 + lcol) * 2);
                ldsm4(ah[mt], r);
                ldsm4(al[mt], r + 128 * 40 * 2);
            }
            uint32_t bf[WNT / 2][4];
            #pragma unroll
            for (int pt = 0; pt < WNT / 2; pt++) {
                uint32_t r = b_base + (uint32_t)(((wn * (BN / 2) + pt * 16 + lrow) * 40 + ks * 16 + lcol) * 2);
                ldsm4(bf[pt], r);
            }
            #pragma unroll
            for (int mt = 0; mt < 2; mt++)
                #pragma unroll
                for (int t = 0; t < WNT; t++) {
                    uint32_t b0 = bf[t >> 1][t & 1], b1 = bf[t >> 1][2 + (t & 1)];
                    mma16816(acc[mt][t], ah[mt], b0, b1);
                    mma16816(acc[mt][t], al[mt], b0, b1);
                }
            #pragma unroll
            for (int pt = 0; pt < WNT / 2; pt++) {
                uint32_t r = b_base + BN * 40 * 2 +
                             (uint32_t)(((wn * (BN / 2) + pt * 16 + lrow) * 40 + ks * 16 + lcol) * 2);
                ldsm4(bf[pt], r);
            }
            #pragma unroll
            for (int mt = 0; mt < 2; mt++)
                #pragma unroll
                for (int t = 0; t < WNT; t++) {
                    uint32_t b0 = bf[t >> 1][t & 1], b1 = bf[t >> 1][2 + (t & 1)];
                    mma16816(acc[mt][t], ah[mt], b0, b1);
                }
        }
        __syncthreads();
    }
    // ---- epilogue
    int gq = lane >> 2, tg = lane & 3;
    #pragma unroll
    for (int mt = 0; mt < 2; mt++) {
        #pragma unroll
        for (int t = 0; t < WNT; t++) {
            int col = wn * (BN / 2) + t * 8 + tg * 2;
            float u0 = Ub[col], u1 = Ub[col + 1];
            int r0 = row0 + wm * 32 + mt * 16 + gq;
            float v0 = acc[mt][t][0] + u0, v1 = acc[mt][t][1] + u1;
            float v2 = acc[mt][t][2] + u0, v3 = acc[mt][t][3] + u1;
            if (RELU) {
                v0 = fmaxf(v0, 0.f); v1 = fmaxf(v1, 0.f);
                v2 = fmaxf(v2, 0.f); v3 = fmaxf(v3, 0.f);
            }
            if (r0 < M)     *(float2*)&C[(size_t)r0 * BN + col]       = make_float2(v0, v1);
            if (r0 + 8 < M) *(float2*)&C[(size_t)(r0 + 8) * BN + col] = make_float2(v2, v3);
        }
    }
}

// ---------------- mma.sync PQ GEMM: grid.y=0 -> P, 1 -> Q(+Mb) ----------------
template <int INSEL>
__global__ __launch_bounds__(256, 2) void mma_pq(const float* __restrict__ hin,
                                                 const float* __restrict__ Mb, int M) {
    constexpr int KTOT = 128, NCH = 4, BN = 128, WNT = 8;
    __shared__ __align__(16) uint16_t sA[2][128][40];
    __shared__ __align__(16) uint16_t sB[2][BN][40];
    const float* H = sel_in<INSEL>(hin);
    int mat = blockIdx.y;
    float* C = mat ? g_Q : g_P;

    int tid = threadIdx.x, lane = tid & 31, wid = tid >> 5;
    int wm = wid & 3, wn = wid >> 2;
    int row0  = blockIdx.x * 128;
    int arow  = tid >> 1, ahalf = (tid & 1) * 16;
    int gr_a  = row0 + arow;
    bool va   = gr_a < M;

    float acc[2][WNT][4];
    #pragma unroll
    for (int mt = 0; mt < 2; mt++)
        #pragma unroll
        for (int t = 0; t < WNT; t++)
            #pragma unroll
            for (int j = 0; j < 4; j++) acc[mt][t][j] = 0.f;

    uint32_t a_base = smem_u32(&sA[0][0][0]);
    uint32_t b_base = smem_u32(&sB[0][0][0]);
    int lrow = lane & 15, lcol = (lane >> 4) * 8;

    for (int kt = 0; kt < NCH; kt++) {
        int k0 = kt * 32;
        const float* bp = H + (size_t)gr_a * 128 + k0;
        float4 f[4];
        #pragma unroll
        for (int q = 0; q < 4; q++)
            f[q] = va ? *(const float4*)(bp + ahalf + q * 4)
                      : make_float4(0.f, 0.f, 0.f, 0.f);
        uint4 Hv[2], Lv[2];
        conv16(f, 1.0f, Hv, Lv);
        *(uint4*)&sA[0][arow][ahalf]     = Hv[0];
        *(uint4*)&sA[0][arow][ahalf + 8] = Hv[1];
        *(uint4*)&sA[1][arow][ahalf]     = Lv[0];
        *(uint4*)&sA[1][arow][ahalf + 8] = Lv[1];
        #pragma unroll
        for (int i = tid; i < BN * 8; i += 256) {
            int img = i >= BN * 4;
            int j   = img ? i - BN * 4 : i;
            int n   = j >> 2, q = j & 3;
            const unsigned char* g = img ? g_Blo : g_Bhi;
            uint4 v = *(const uint4*)(g + ((size_t)(mat * 128 + n) * KTOT + k0 + q * 8) * 2);
            *(uint4*)&sB[img][n][q * 8] = v;
        }
        __syncthreads();
        #pragma unroll
        for (int ks = 0; ks < 2; ks++) {
            uint32_t ah[2][4], al[2][4];
            #pragma unroll
            for (int mt = 0; mt < 2; mt++) {
                uint32_t r = a_base + (uint32_t)(((wm * 32 + mt * 16 + lrow) * 40 + ks * 16 + lcol) * 2);
                ldsm4(ah[mt], r);
                ldsm4(al[mt], r + 128 * 40 * 2);
            }
            uint32_t bf[WNT / 2][4];
            #pragma unroll
            for (int pt = 0; pt < WNT / 2; pt++) {
                uint32_t r = b_base + (uint32_t)(((wn * 64 + pt * 16 + lrow) * 40 + ks * 16 + lcol) * 2);
                ldsm4(bf[pt], r);
            }
            #pragma unroll
            for (int mt = 0; mt < 2; mt++)
                #pragma unroll
                for (int t = 0; t < WNT; t++) {
                    uint32_t b0 = bf[t >> 1][t & 1], b1 = bf[t >> 1][2 + (t & 1)];
                    mma16816(acc[mt][t], ah[mt], b0, b1);
                    mma16816(acc[mt][t], al[mt], b0, b1);
                }
            #pragma unroll
            for (int pt = 0; pt < WNT / 2; pt++) {
                uint32_t r = b_base + BN * 40 * 2 +
                             (uint32_t)(((wn * 64 + pt * 16 + lrow) * 40 + ks * 16 + lcol) * 2);
                ldsm4(bf[pt], r);
            }
            #pragma unroll
            for (int mt = 0; mt < 2; mt++)
                #pragma unroll
                for (int t = 0; t < WNT; t++) {
                    uint32_t b0 = bf[t >> 1][t & 1], b1 = bf[t >> 1][2 + (t & 1)];
                    mma16816(acc[mt][t], ah[mt], b0, b1);
                }
        }
        __syncthreads();
    }
    int gq = lane >> 2, tg = lane & 3;
    #pragma unroll
    for (int mt = 0; mt < 2; mt++) {
        #pragma unroll
        for (int t = 0; t < WNT; t++) {
            int col = wn * 64 + t * 8 + tg * 2;
            float u0 = mat ? Mb[col] : 0.f;
            float u1 = mat ? Mb[col + 1] : 0.f;
            int r0 = row0 + wm * 32 + mt * 16 + gq;
            if (r0 < M)
                *(float2*)&C[(size_t)r0 * 128 + col] =
                    make_float2(acc[mt][t][0] + u0, acc[mt][t][1] + u1);
            if (r0 + 8 < M)
                *(float2*)&C[(size_t)(r0 + 8) * 128 + col] =
                    make_float2(acc[mt][t][2] + u0, acc[mt][t][3] + u1);
        }
    }
}

// ---------------- CSR aggregation: warp per node, float4 per lane ----------------
__global__ void agg_kernel(int n) {
    int gw   = (blockIdx.x * blockDim.x + threadIdx.x) >> 5;
    int lane = threadIdx.x & 31;
    if (gw >= n) return;
    int s = g_off[gw], e = g_off[gw + 1];
    int c = lane * 4;
    float4 sum = make_float4(0.f, 0.f, 0.f, 0.f);
    float4 mn  = make_float4(1e30f, 1e30f, 1e30f, 1e30f);
    float4 mx  = make_float4(-1e30f, -1e30f, -1e30f, -1e30f);
    for (int i = s; i < e; i++) {
        int r    = g_csr[i];
        float4 v = *(const float4*)&g_P[(size_t)r * 128 + c];
        sum.x += v.x; sum.y += v.y; sum.z += v.z; sum.w += v.w;
        mn.x = fminf(mn.x, v.x); mn.y = fminf(mn.y, v.y);
        mn.z = fminf(mn.z, v.z); mn.w = fminf(mn.w, v.w);
        mx.x = fmaxf(mx.x, v.x); mx.y = fmaxf(mx.y, v.y);
        mx.z = fmaxf(mx.z, v.z); mx.w = fmaxf(mx.w, v.w);
    }
    float4 q = *(const float4*)&g_Q[(size_t)gw * 128 + c];
    float4 me, on, ox;
    int d = e - s;
    if (d > 0) {
        float inv = 1.0f / (float)d;
        me.x = sum.x * inv + q.x; me.y = sum.y * inv + q.y;
        me.z = sum.z * inv + q.z; me.w = sum.w * inv + q.w;
        on.x = mn.x + q.x; on.y = mn.y + q.y; on.z = mn.z + q.z; on.w = mn.w + q.w;
        ox.x = mx.x + q.x; ox.y = mx.y + q.y; ox.z = mx.z + q.z; ox.w = mx.w + q.w;
    } else {
        me = make_float4(0.f, 0.f, 0.f, 0.f);
        on = me; ox = me;
    }
    *(float4*)&g_agg[(size_t)gw * 384 + c]       = me;
    *(float4*)&g_agg[(size_t)gw * 384 + 128 + c] = on;
    *(float4*)&g_agg[(size_t)gw * 384 + 256 + c] = ox;
}

// ---------------- host launcher ----------------
extern "C" void kernel_launch(void* const* d_in, const int* in_sizes, int n_in,
                              void* d_out, int out_size) {
    const float* x   = (const float*)d_in[0];
    const void*  src = d_in[1];
    const void*  dst = d_in[2];
    const float* M0w = (const float*)d_in[3];
    const float* M0b = (const float*)d_in[4];
    const float* U0w = (const float*)d_in[5];
    const float* U0b = (const float*)d_in[6];
    const float* M1w = (const float*)d_in[7];
    const float* M1b = (const float*)d_in[8];
    const float* U1w = (const float*)d_in[9];
    const float* U1b = (const float*)d_in[10];
    const float* M2w = (const float*)d_in[11];
    const float* M2b = (const float*)d_in[12];
    const float* U2w = (const float*)d_in[13];
    const float* U2b = (const float*)d_in[14];

    int n = in_sizes[0] / 128;
    int e = in_sizes[1];
    if (n > NN) n = NN;
    if (e > NE) e = NE;

    int gE = (e + 255) / 256;
    int gN = (n + 255) / 256;
    int gM = (n + 127) / 128;
    int gA = (n * 32 + 255) / 256;

    // CSR build + node scalars
    detect_kernel<<<1, 256>>>(dst, e, n);
    zero_deg<<<gN, 256>>>(n);
    hist_kernel<<<gE, 256>>>(dst, e);
    scan_kernel2<<<1, 1024>>>(n);
    scatter_kernel<<<gE, 256>>>(src, dst, e);

    // layer 0: in = x, out = g_h1
    prepack_pq2<<<128, 256>>>(M0w);
    mma_pq<0><<<dim3(gM, 2), 256>>>(x, M0b, n);
    agg_kernel<<<gA, 256>>>(n);
    prepack_upd2<<<(1280 * 128 + 255) / 256, 256>>>(U0w, 128);
    mma_update<0, 1, 128, true><<<gM, 256>>>(x, U0b, nullptr, n);

    // layer 1: in = g_h1, out = g_h2
    prepack_pq2<<<128, 256>>>(M1w);
    mma_pq<1><<<dim3(gM, 2), 256>>>(nullptr, M1b, n);
    agg_kernel<<<gA, 256>>>(n);
    prepack_upd2<<<(1280 * 128 + 255) / 256, 256>>>(U1w, 128);
    mma_update<1, 2, 128, true><<<gM, 256>>>(nullptr, U1b, nullptr, n);

    // layer 2: in = g_h2, out = d_out (N=64, no relu)
    prepack_pq2<<<128, 256>>>(M2w);
    mma_pq<2><<<dim3(gM, 2), 256>>>(nullptr, M2b, n);
    agg_kernel<<<gA, 256>>>(n);
    prepack_upd2<<<(1280 * 64 + 255) / 256, 256>>>(U2w, 64);
    mma_update<2, 0, 64, false><<<gM, 256>>>(nullptr, U2b, (float*)d_out, n);
}

// round 8
// speedup vs baseline: 2.0691x; 1.1832x over previous
#include <cuda_runtime.h>
#include <cuda_bf16.h>
#include <cstdint>
#include <math.h>

#define NN 50000
#define NE 800000

// ---------------- scratch (static device globals; no allocation) ----------------
__device__ int   g_is64;
__device__ int   g_deg[NN];
__device__ int   g_off[NN + 1];
__device__ int   g_cur[NN];
__device__ int   g_csr[NE];
__device__ int   g_bsum[64];
__device__ float g_amp[NN];
__device__ float g_att[NN];
__device__ float g_P[NN * 128];
__device__ float g_Q[NN * 128];
__device__ float g_agg[NN * 384];
__device__ float g_h1[NN * 128];
__device__ float g_h2[NN * 128];
// prepacked weights: [N][K] row-major bf16, hi and lo images
__device__ unsigned char g_Bhi[1280 * 128 * 2];
__device__ unsigned char g_Blo[1280 * 128 * 2];

// ---------------- helpers ----------------
__device__ __forceinline__ uint32_t smem_u32(const void* p) {
    uint32_t a;
    asm("{ .reg .u64 t; cvta.to.shared.u64 t, %1; cvt.u32.u64 %0, t; }"
        : "=r"(a) : "l"(p));
    return a;
}
__device__ __forceinline__ void ldsm4(uint32_t* r, uint32_t addr) {
    asm volatile("ldmatrix.sync.aligned.m8n8.x4.shared.b16 {%0,%1,%2,%3}, [%4];"
                 : "=r"(r[0]), "=r"(r[1]), "=r"(r[2]), "=r"(r[3]) : "r"(addr));
}
__device__ __forceinline__ void mma16816(float* c, const uint32_t* a,
                                         uint32_t b0, uint32_t b1) {
    asm volatile("mma.sync.aligned.m16n8k16.row.col.f32.bf16.bf16.f32 "
                 "{%0,%1,%2,%3}, {%4,%5,%6,%7}, {%8,%9}, {%0,%1,%2,%3};"
                 : "+f"(c[0]), "+f"(c[1]), "+f"(c[2]), "+f"(c[3])
                 : "r"(a[0]), "r"(a[1]), "r"(a[2]), "r"(a[3]), "r"(b0), "r"(b1));
}
__device__ __forceinline__ void cp_async16(uint32_t daddr, const void* gptr) {
    asm volatile("cp.async.cg.shared.global [%0], [%1], 16;"
                 :: "r"(daddr), "l"(gptr));
}
#define CP_COMMIT() asm volatile("cp.async.commit_group;" ::: "memory")
#define CP_WAIT1()  asm volatile("cp.async.wait_group 1;" ::: "memory")
#define CP_WAIT0()  asm volatile("cp.async.wait_group 0;" ::: "memory")

// 16 fp32 -> bf16 hi/lo (scaled), packed as 2+2 uint4
__device__ __forceinline__ void conv16(const float4* f, float s, uint4* Hv, uint4* Lv) {
    uint32_t hw[8], lw[8];
    #pragma unroll
    for (int q = 0; q < 4; q++) {
        float v[4] = {f[q].x * s, f[q].y * s, f[q].z * s, f[q].w * s};
        uint16_t hb[4], lb[4];
        #pragma unroll
        for (int i = 0; i < 4; i++) {
            __nv_bfloat16 h = __float2bfloat16(v[i]);
            float hf        = __bfloat162float(h);
            __nv_bfloat16 l = __float2bfloat16(v[i] - hf);
            hb[i] = __bfloat16_as_ushort(h);
            lb[i] = __bfloat16_as_ushort(l);
        }
        hw[q * 2 + 0] = (uint32_t)hb[0] | ((uint32_t)hb[1] << 16);
        hw[q * 2 + 1] = (uint32_t)hb[2] | ((uint32_t)hb[3] << 16);
        lw[q * 2 + 0] = (uint32_t)lb[0] | ((uint32_t)lb[1] << 16);
        lw[q * 2 + 1] = (uint32_t)lb[2] | ((uint32_t)lb[3] << 16);
    }
    Hv[0] = make_uint4(hw[0], hw[1], hw[2], hw[3]);
    Hv[1] = make_uint4(hw[4], hw[5], hw[6], hw[7]);
    Lv[0] = make_uint4(lw[0], lw[1], lw[2], lw[3]);
    Lv[1] = make_uint4(lw[4], lw[5], lw[6], lw[7]);
}

// ---------------- index-width detection ----------------
__global__ void detect_kernel(const void* dst, int e, int n) {
    __shared__ int bad;
    if (threadIdx.x == 0) bad = 0;
    __syncthreads();
    int k = e < 1024 ? e : 1024;
    const long long* p = (const long long*)dst;
    for (int i = threadIdx.x; i < k; i += blockDim.x) {
        long long v = p[i];
        if (v < 0 || v >= (long long)n) atomicExch(&bad, 1);
    }
    __syncthreads();
    if (threadIdx.x == 0) g_is64 = bad ? 0 : 1;
}
__device__ __forceinline__ int load_idx(const void* p, int i) {
    if (g_is64) return (int)((const long long*)p)[i];
    return ((const int*)p)[i];
}

// ---------------- CSR build ----------------
__global__ void zero_deg(int n) {
    int i = blockIdx.x * blockDim.x + threadIdx.x;
    if (i < n) g_deg[i] = 0;
}
__global__ void hist_kernel(const void* __restrict__ dst, int e) {
    int i = blockIdx.x * blockDim.x + threadIdx.x;
    if (i < e) atomicAdd(&g_deg[load_idx(dst, i)], 1);
}

// ---- parallel scan: p1 block sums, p2 scan of block sums, p3 finalize ----
__global__ void scan_p1(int n) {  // grid=nb, block=256, 1024 elems/block
    int base = blockIdx.x * 1024 + threadIdx.x * 4;
    int s = 0;
    #pragma unroll
    for (int j = 0; j < 4; j++) {
        int i = base + j;
        if (i < n) s += g_deg[i];
    }
    #pragma unroll
    for (int o = 16; o; o >>= 1) s += __shfl_down_sync(0xFFFFFFFFu, s, o);
    __shared__ int ws[8];
    if ((threadIdx.x & 31) == 0) ws[threadIdx.x >> 5] = s;
    __syncthreads();
    if (threadIdx.x == 0) {
        int t = 0;
        #pragma unroll
        for (int w = 0; w < 8; w++) t += ws[w];
        g_bsum[blockIdx.x] = t;
    }
}
__global__ void scan_p2(int nb, int n) {  // 1 block, 64 threads
    int tid = threadIdx.x;
    int v = tid < nb ? g_bsum[tid] : 0;
    __shared__ int tmp[64];
    tmp[tid] = v;
    __syncthreads();
    #pragma unroll
    for (int o = 1; o < 64; o <<= 1) {
        int t = tid >= o ? tmp[tid - o] : 0;
        __syncthreads();
        tmp[tid] += t;
        __syncthreads();
    }
    if (tid < nb) g_bsum[tid] = tmp[tid] - v;  // exclusive block base
    if (tid == 0) g_off[n] = tmp[63];          // grand total
}
__global__ void scan_p3(int n) {  // grid=nb, block=256
    int tid  = threadIdx.x;
    int base = blockIdx.x * 1024 + tid * 4;
    int d[4], s = 0;
    #pragma unroll
    for (int j = 0; j < 4; j++) {
        int i = base + j;
        d[j] = (i < n) ? g_deg[i] : 0;
        s += d[j];
    }
    int lane = tid & 31, w = tid >> 5;
    int incl = s;
    #pragma unroll
    for (int o = 1; o < 32; o <<= 1) {
        int t = __shfl_up_sync(0xFFFFFFFFu, incl, o);
        if (lane >= o) incl += t;
    }
    __shared__ int ws[8];
    if (lane == 31) ws[w] = incl;
    __syncthreads();
    if (tid == 0) {
        int acc = 0;
        #pragma unroll
        for (int q = 0; q < 8; q++) { int t = ws[q]; ws[q] = acc; acc += t; }
    }
    __syncthreads();
    int run = incl - s + ws[w] + g_bsum[blockIdx.x];
    #pragma unroll
    for (int j = 0; j < 4; j++) {
        int i = base + j;
        if (i < n) {
            g_off[i] = run;
            g_cur[i] = run;
            float ld = logf((float)d[j] + 1.0f);
            g_amp[i] = ld * (1.0f / 3.0f);
            g_att[i] = 3.0f / fmaxf(ld, 1e-6f);
            run += d[j];
        }
    }
}

__global__ void scatter_kernel(const void* __restrict__ src,
                               const void* __restrict__ dst, int e) {
    int i = blockIdx.x * blockDim.x + threadIdx.x;
    if (i < e) {
        int d   = load_idx(dst, i);
        int pos = atomicAdd(&g_cur[d], 1);
        g_csr[pos] = load_idx(src, i);
    }
}

// ---------------- weight prepack: fp32 [K][N] -> bf16 hi/lo [N][K] ----------------
__global__ void prepack_upd2(const float* __restrict__ Uw, int N) {
    int idx = blockIdx.x * blockDim.x + threadIdx.x;
    if (idx >= 1280 * N) return;
    int k = idx / N, n = idx % N;
    float v = Uw[idx];
    __nv_bfloat16 h = __float2bfloat16(v);
    float hf        = __bfloat162float(h);
    __nv_bfloat16 l = __float2bfloat16(v - hf);
    size_t pos = (size_t)n * 1280 + k;
    ((unsigned short*)g_Bhi)[pos] = __bfloat16_as_ushort(h);
    ((unsigned short*)g_Blo)[pos] = __bfloat16_as_ushort(l);
}

// PQ: Mw [256 x 128]; packed B rows: n<128 -> P (Mw top), n>=128 -> Q (Mw bottom)
__global__ void prepack_pq2(const float* __restrict__ Mw) {
    int idx = blockIdx.x * blockDim.x + threadIdx.x;
    if (idx >= 256 * 128) return;
    int n = idx >> 7, k = idx & 127;
    int mat = n >> 7, nn = n & 127;
    float v = Mw[(mat * 128 + k) * 128 + nn];
    __nv_bfloat16 h = __float2bfloat16(v);
    float hf        = __bfloat162float(h);
    __nv_bfloat16 l = __float2bfloat16(v - hf);
    size_t pos = (size_t)n * 128 + k;
    ((unsigned short*)g_Bhi)[pos] = __bfloat16_as_ushort(h);
    ((unsigned short*)g_Blo)[pos] = __bfloat16_as_ushort(l);
}

// ---------------- input selection helper ----------------
template <int SEL>
__device__ __forceinline__ const float* sel_in(const float* a) {
    if constexpr (SEL == 1) return g_h1;
    else if constexpr (SEL == 2) return g_h2;
    else return a;
}

// ---------------- mma.sync update GEMM, cp.async double-buffered B ----------------
// C[M x BN] = [h|agg|agg*amp|agg*att](M x 1280) @ Uw(1280 x BN) + Ub, bf16x3 fp32-acc
// dyn smem: sA [2][128][40] (20480B) | sB [2 stages][2 imgs][BN][40]
template <int INSEL, int OUTSEL, int BN, bool RELU>
__global__ __launch_bounds__(256, 2) void mma_update(const float* __restrict__ hin,
                                                     const float* __restrict__ Ub,
                                                     float* __restrict__ outp, int M) {
    constexpr int KTOT = 1280, NCH = 40, WNT = BN / 16;
    constexpr int SB_STAGE = 2 * BN * 40;  // uint16 units per stage
    extern __shared__ __align__(16) char dyn[];
    uint16_t* sA = (uint16_t*)dyn;                  // [2][128][40]
    uint16_t* sB = (uint16_t*)(dyn + 20480);        // [2][2][BN][40]
    const float* H = sel_in<INSEL>(hin);
    float* C;
    if constexpr (OUTSEL == 1) C = g_h1;
    else if constexpr (OUTSEL == 2) C = g_h2;
    else C = outp;

    int tid = threadIdx.x, lane = tid & 31, wid = tid >> 5;
    int wm = wid & 3, wn = wid >> 2;
    int row0  = blockIdx.x * 128;
    int arow  = tid >> 1, ahalf = (tid & 1) * 16;
    int gr_a  = row0 + arow;
    bool va   = gr_a < M;
    float s_amp = va ? g_amp[gr_a] : 0.f;
    float s_att = va ? g_att[gr_a] : 0.f;

    float acc[2][WNT][4];
    #pragma unroll
    for (int mt = 0; mt < 2; mt++)
        #pragma unroll
        for (int t = 0; t < WNT; t++)
            #pragma unroll
            for (int j = 0; j < 4; j++) acc[mt][t][j] = 0.f;

    uint32_t a_base = smem_u32(sA);
    uint32_t b_base = smem_u32(sB);
    int lrow = lane & 15, lcol = (lane >> 4) * 8;

    // B fill via cp.async into stage st for K-chunk k0
    auto fillB = [&](int k0, int st) {
        uint32_t sbase = b_base + (uint32_t)(st * SB_STAGE * 2);
        #pragma unroll
        for (int i = tid; i < BN * 8; i += 256) {
            int img = i >= BN * 4;
            int j   = img ? i - BN * 4 : i;
            int n   = j >> 2, q = j & 3;
            const unsigned char* g = img ? g_Blo : g_Bhi;
            uint32_t daddr = sbase + (uint32_t)(((img * BN + n) * 40 + q * 8) * 2);
            cp_async16(daddr, g + ((size_t)n * KTOT + k0 + q * 8) * 2);
        }
        CP_COMMIT();
    };

    fillB(0, 0);

    for (int kt = 0; kt < NCH; kt++) {
        int k0 = kt * 32;
        // ---- A fill: region-select + hi/lo split (sA safe: loop-end sync)
        const float* bp;
        float s = 1.f;
        if (k0 < 128)      bp = H + (size_t)gr_a * 128 + k0;
        else if (k0 < 512) bp = g_agg + (size_t)gr_a * 384 + (k0 - 128);
        else if (k0 < 896) { bp = g_agg + (size_t)gr_a * 384 + (k0 - 512); s = s_amp; }
        else               { bp = g_agg + (size_t)gr_a * 384 + (k0 - 896); s = s_att; }
        float4 f[4];
        #pragma unroll
        for (int q = 0; q < 4; q++)
            f[q] = va ? *(const float4*)(bp + ahalf + q * 4)
                      : make_float4(0.f, 0.f, 0.f, 0.f);
        uint4 Hv[2], Lv[2];
        conv16(f, s, Hv, Lv);
        *(uint4*)&sA[(size_t)arow * 40 + ahalf]              = Hv[0];
        *(uint4*)&sA[(size_t)arow * 40 + ahalf + 8]          = Hv[1];
        *(uint4*)&sA[(size_t)(128 + arow) * 40 + ahalf]      = Lv[0];
        *(uint4*)&sA[(size_t)(128 + arow) * 40 + ahalf + 8]  = Lv[1];
        // ---- prefetch next B stage, wait for current
        if (kt + 1 < NCH) { fillB(k0 + 32, (kt + 1) & 1); CP_WAIT1(); }
        else              { CP_WAIT0(); }
        __syncthreads();
        // ---- mma on stage kt&1
        uint32_t bst = b_base + (uint32_t)((kt & 1) * SB_STAGE * 2);
        #pragma unroll
        for (int ks = 0; ks < 2; ks++) {
            uint32_t ah[2][4], al[2][4];
            #pragma unroll
            for (int mt = 0; mt < 2; mt++) {
                uint32_t r = a_base + (uint32_t)(((wm * 32 + mt * 16 + lrow) * 40 + ks * 16 + lcol) * 2);
                ldsm4(ah[mt], r);
                ldsm4(al[mt], r + 128 * 40 * 2);
            }
            uint32_t bf[WNT / 2][4];
            #pragma unroll
            for (int pt = 0; pt < WNT / 2; pt++) {
                uint32_t r = bst + (uint32_t)(((wn * (BN / 2) + pt * 16 + lrow) * 40 + ks * 16 + lcol) * 2);
                ldsm4(bf[pt], r);
            }
            #pragma unroll
            for (int mt = 0; mt < 2; mt++)
                #pragma unroll
                for (int t = 0; t < WNT; t++) {
                    uint32_t b0 = bf[t >> 1][t & 1], b1 = bf[t >> 1][2 + (t & 1)];
                    mma16816(acc[mt][t], ah[mt], b0, b1);
                    mma16816(acc[mt][t], al[mt], b0, b1);
                }
            #pragma unroll
            for (int pt = 0; pt < WNT / 2; pt++) {
                uint32_t r = bst + (uint32_t)(BN * 40 * 2) +
                             (uint32_t)(((wn * (BN / 2) + pt * 16 + lrow) * 40 + ks * 16 + lcol) * 2);
                ldsm4(bf[pt], r);
            }
            #pragma unroll
            for (int mt = 0; mt < 2; mt++)
                #pragma unroll
                for (int t = 0; t < WNT; t++) {
                    uint32_t b0 = bf[t >> 1][t & 1], b1 = bf[t >> 1][2 + (t & 1)];
                    mma16816(acc[mt][t], ah[mt], b0, b1);
                }
        }
        __syncthreads();
    }
    // ---- epilogue
    int gq = lane >> 2, tg = lane & 3;
    #pragma unroll
    for (int mt = 0; mt < 2; mt++) {
        #pragma unroll
        for (int t = 0; t < WNT; t++) {
            int col = wn * (BN / 2) + t * 8 + tg * 2;
            float u0 = Ub[col], u1 = Ub[col + 1];
            int r0 = row0 + wm * 32 + mt * 16 + gq;
            float v0 = acc[mt][t][0] + u0, v1 = acc[mt][t][1] + u1;
            float v2 = acc[mt][t][2] + u0, v3 = acc[mt][t][3] + u1;
            if (RELU) {
                v0 = fmaxf(v0, 0.f); v1 = fmaxf(v1, 0.f);
                v2 = fmaxf(v2, 0.f); v3 = fmaxf(v3, 0.f);
            }
            if (r0 < M)     *(float2*)&C[(size_t)r0 * BN + col]       = make_float2(v0, v1);
            if (r0 + 8 < M) *(float2*)&C[(size_t)(r0 + 8) * BN + col] = make_float2(v2, v3);
        }
    }
}

// ---------------- mma.sync PQ GEMM: grid.y=0 -> P, 1 -> Q(+Mb) ----------------
template <int INSEL>
__global__ __launch_bounds__(256, 2) void mma_pq(const float* __restrict__ hin,
                                                 const float* __restrict__ Mb, int M) {
    constexpr int KTOT = 128, NCH = 4, BN = 128, WNT = 8;
    __shared__ __align__(16) uint16_t sA[2][128][40];
    __shared__ __align__(16) uint16_t sB[2][BN][40];
    const float* H = sel_in<INSEL>(hin);
    int mat = blockIdx.y;
    float* C = mat ? g_Q : g_P;

    int tid = threadIdx.x, lane = tid & 31, wid = tid >> 5;
    int wm = wid & 3, wn = wid >> 2;
    int row0  = blockIdx.x * 128;
    int arow  = tid >> 1, ahalf = (tid & 1) * 16;
    int gr_a  = row0 + arow;
    bool va   = gr_a < M;

    float acc[2][WNT][4];
    #pragma unroll
    for (int mt = 0; mt < 2; mt++)
        #pragma unroll
        for (int t = 0; t < WNT; t++)
            #pragma unroll
            for (int j = 0; j < 4; j++) acc[mt][t][j] = 0.f;

    uint32_t a_base = smem_u32(&sA[0][0][0]);
    uint32_t b_base = smem_u32(&sB[0][0][0]);
    int lrow = lane & 15, lcol = (lane >> 4) * 8;

    for (int kt = 0; kt < NCH; kt++) {
        int k0 = kt * 32;
        const float* bp = H + (size_t)gr_a * 128 + k0;
        float4 f[4];
        #pragma unroll
        for (int q = 0; q < 4; q++)
            f[q] = va ? *(const float4*)(bp + ahalf + q * 4)
                      : make_float4(0.f, 0.f, 0.f, 0.f);
        uint4 Hv[2], Lv[2];
        conv16(f, 1.0f, Hv, Lv);
        *(uint4*)&sA[0][arow][ahalf]     = Hv[0];
        *(uint4*)&sA[0][arow][ahalf + 8] = Hv[1];
        *(uint4*)&sA[1][arow][ahalf]     = Lv[0];
        *(uint4*)&sA[1][arow][ahalf + 8] = Lv[1];
        #pragma unroll
        for (int i = tid; i < BN * 8; i += 256) {
            int img = i >= BN * 4;
            int j   = img ? i - BN * 4 : i;
            int n   = j >> 2, q = j & 3;
            const unsigned char* g = img ? g_Blo : g_Bhi;
            uint4 v = *(const uint4*)(g + ((size_t)(mat * 128 + n) * KTOT + k0 + q * 8) * 2);
            *(uint4*)&sB[img][n][q * 8] = v;
        }
        __syncthreads();
        #pragma unroll
        for (int ks = 0; ks < 2; ks++) {
            uint32_t ah[2][4], al[2][4];
            #pragma unroll
            for (int mt = 0; mt < 2; mt++) {
                uint32_t r = a_base + (uint32_t)(((wm * 32 + mt * 16 + lrow) * 40 + ks * 16 + lcol) * 2);
                ldsm4(ah[mt], r);
                ldsm4(al[mt], r + 128 * 40 * 2);
            }
            uint32_t bf[WNT / 2][4];
            #pragma unroll
            for (int pt = 0; pt < WNT / 2; pt++) {
                uint32_t r = b_base + (uint32_t)(((wn * 64 + pt * 16 + lrow) * 40 + ks * 16 + lcol) * 2);
                ldsm4(bf[pt], r);
            }
            #pragma unroll
            for (int mt = 0; mt < 2; mt++)
                #pragma unroll
                for (int t = 0; t < WNT; t++) {
                    uint32_t b0 = bf[t >> 1][t & 1], b1 = bf[t >> 1][2 + (t & 1)];
                    mma16816(acc[mt][t], ah[mt], b0, b1);
                    mma16816(acc[mt][t], al[mt], b0, b1);
                }
            #pragma unroll
            for (int pt = 0; pt < WNT / 2; pt++) {
                uint32_t r = b_base + BN * 40 * 2 +
                             (uint32_t)(((wn * 64 + pt * 16 + lrow) * 40 + ks * 16 + lcol) * 2);
                ldsm4(bf[pt], r);
            }
            #pragma unroll
            for (int mt = 0; mt < 2; mt++)
                #pragma unroll
                for (int t = 0; t < WNT; t++) {
                    uint32_t b0 = bf[t >> 1][t & 1], b1 = bf[t >> 1][2 + (t & 1)];
                    mma16816(acc[mt][t], ah[mt], b0, b1);
                }
        }
        __syncthreads();
    }
    int gq = lane >> 2, tg = lane & 3;
    #pragma unroll
    for (int mt = 0; mt < 2; mt++) {
        #pragma unroll
        for (int t = 0; t < WNT; t++) {
            int col = wn * 64 + t * 8 + tg * 2;
            float u0 = mat ? Mb[col] : 0.f;
            float u1 = mat ? Mb[col + 1] : 0.f;
            int r0 = row0 + wm * 32 + mt * 16 + gq;
            if (r0 < M)
                *(float2*)&C[(size_t)r0 * 128 + col] =
                    make_float2(acc[mt][t][0] + u0, acc[mt][t][1] + u1);
            if (r0 + 8 < M)
                *(float2*)&C[(size_t)(r0 + 8) * 128 + col] =
                    make_float2(acc[mt][t][2] + u0, acc[mt][t][3] + u1);
        }
    }
}

// ---------------- CSR aggregation: warp per node, float4 per lane ----------------
__global__ void agg_kernel(int n) {
    int gw   = (blockIdx.x * blockDim.x + threadIdx.x) >> 5;
    int lane = threadIdx.x & 31;
    if (gw >= n) return;
    int s = g_off[gw], e = g_off[gw + 1];
    int c = lane * 4;
    float4 sum = make_float4(0.f, 0.f, 0.f, 0.f);
    float4 mn  = make_float4(1e30f, 1e30f, 1e30f, 1e30f);
    float4 mx  = make_float4(-1e30f, -1e30f, -1e30f, -1e30f);
    for (int i = s; i < e; i++) {
        int r    = g_csr[i];
        float4 v = *(const float4*)&g_P[(size_t)r * 128 + c];
        sum.x += v.x; sum.y += v.y; sum.z += v.z; sum.w += v.w;
        mn.x = fminf(mn.x, v.x); mn.y = fminf(mn.y, v.y);
        mn.z = fminf(mn.z, v.z); mn.w = fminf(mn.w, v.w);
        mx.x = fmaxf(mx.x, v.x); mx.y = fmaxf(mx.y, v.y);
        mx.z = fmaxf(mx.z, v.z); mx.w = fmaxf(mx.w, v.w);
    }
    float4 q = *(const float4*)&g_Q[(size_t)gw * 128 + c];
    float4 me, on, ox;
    int d = e - s;
    if (d > 0) {
        float inv = 1.0f / (float)d;
        me.x = sum.x * inv + q.x; me.y = sum.y * inv + q.y;
        me.z = sum.z * inv + q.z; me.w = sum.w * inv + q.w;
        on.x = mn.x + q.x; on.y = mn.y + q.y; on.z = mn.z + q.z; on.w = mn.w + q.w;
        ox.x = mx.x + q.x; ox.y = mx.y + q.y; ox.z = mx.z + q.z; ox.w = mx.w + q.w;
    } else {
        me = make_float4(0.f, 0.f, 0.f, 0.f);
        on = me; ox = me;
    }
    *(float4*)&g_agg[(size_t)gw * 384 + c]       = me;
    *(float4*)&g_agg[(size_t)gw * 384 + 128 + c] = on;
    *(float4*)&g_agg[(size_t)gw * 384 + 256 + c] = ox;
}

// ---------------- host launcher ----------------
extern "C" void kernel_launch(void* const* d_in, const int* in_sizes, int n_in,
                              void* d_out, int out_size) {
    const float* x   = (const float*)d_in[0];
    const void*  src = d_in[1];
    const void*  dst = d_in[2];
    const float* M0w = (const float*)d_in[3];
    const float* M0b = (const float*)d_in[4];
    const float* U0w = (const float*)d_in[5];
    const float* U0b = (const float*)d_in[6];
    const float* M1w = (const float*)d_in[7];
    const float* M1b = (const float*)d_in[8];
    const float* U1w = (const float*)d_in[9];
    const float* U1b = (const float*)d_in[10];
    const float* M2w = (const float*)d_in[11];
    const float* M2b = (const float*)d_in[12];
    const float* U2w = (const float*)d_in[13];
    const float* U2b = (const float*)d_in[14];

    int n = in_sizes[0] / 128;
    int e = in_sizes[1];
    if (n > NN) n = NN;
    if (e > NE) e = NE;

    const int UPD_SMEM_H = 20480 + 2 * 2 * 128 * 40 * 2;  // 61440 (BN=128)
    const int UPD_SMEM_L = 20480 + 2 * 2 * 64 * 40 * 2;   // 40960 (BN=64)
    cudaFuncSetAttribute(mma_update<0, 1, 128, true>,
                         cudaFuncAttributeMaxDynamicSharedMemorySize, UPD_SMEM_H);
    cudaFuncSetAttribute(mma_update<1, 2, 128, true>,
                         cudaFuncAttributeMaxDynamicSharedMemorySize, UPD_SMEM_H);
    cudaFuncSetAttribute(mma_update<2, 0, 64, false>,
                         cudaFuncAttributeMaxDynamicSharedMemorySize, UPD_SMEM_L);

    int gE = (e + 255) / 256;
    int gN = (n + 255) / 256;
    int gM = (n + 127) / 128;
    int gA = (n * 32 + 255) / 256;
    int nb = (n + 1023) / 1024;

    // CSR build + node scalars
    detect_kernel<<<1, 256>>>(dst, e, n);
    zero_deg<<<gN, 256>>>(n);
    hist_kernel<<<gE, 256>>>(dst, e);
    scan_p1<<<nb, 256>>>(n);
    scan_p2<<<1, 64>>>(nb, n);
    scan_p3<<<nb, 256>>>(n);
    scatter_kernel<<<gE, 256>>>(src, dst, e);

    // layer 0: in = x, out = g_h1
    prepack_pq2<<<128, 256>>>(M0w);
    mma_pq<0><<<dim3(gM, 2), 256>>>(x, M0b, n);
    agg_kernel<<<gA, 256>>>(n);
    prepack_upd2<<<(1280 * 128 + 255) / 256, 256>>>(U0w, 128);
    mma_update<0, 1, 128, true><<<gM, 256, UPD_SMEM_H>>>(x, U0b, nullptr, n);

    // layer 1: in = g_h1, out = g_h2
    prepack_pq2<<<128, 256>>>(M1w);
    mma_pq<1><<<dim3(gM, 2), 256>>>(nullptr, M1b, n);
    agg_kernel<<<gA, 256>>>(n);
    prepack_upd2<<<(1280 * 128 + 255) / 256, 256>>>(U1w, 128);
    mma_update<1, 2, 128, true><<<gM, 256, UPD_SMEM_H>>>(nullptr, U1b, nullptr, n);

    // layer 2: in = g_h2, out = d_out (N=64, no relu)
    prepack_pq2<<<128, 256>>>(M2w);
    mma_pq<2><<<dim3(gM, 2), 256>>>(nullptr, M2b, n);
    agg_kernel<<<gA, 256>>>(n);
    prepack_upd2<<<(1280 * 64 + 255) / 256, 256>>>(U2w, 64);
    mma_update<2, 0, 64, false><<<gM, 256, UPD_SMEM_L>>>(nullptr, U2b, (float*)d_out, n);
}

// round 9
// speedup vs baseline: 2.2622x; 1.0933x over previous
#include <cuda_runtime.h>
#include <cuda_bf16.h>
#include <cstdint>
#include <math.h>

#define NN 50000
#define NE 800000

// ---------------- scratch (static device globals; no allocation) ----------------
__device__ int   g_is64;
__device__ int   g_deg[NN];
__device__ int   g_off[NN + 1];
__device__ int   g_cur[NN];
__device__ int   g_csr[NE];
__device__ int   g_bsum[64];
__device__ float g_amp[NN];
__device__ float g_att[NN];
__device__ float g_P[NN * 128];
__device__ float g_Q[NN * 128];
__device__ float g_agg[NN * 384];
__device__ float g_h1[NN * 128];
__device__ float g_h2[NN * 128];
// prepacked weights, PER LAYER (so prepacks are independent of compute):
// PQ: [256 rows (P|Q)][128 K], update: [N rows][1280 K]
__device__ unsigned short g_PQhi[3][256 * 128];
__device__ unsigned short g_PQlo[3][256 * 128];
__device__ unsigned short g_Uhi[3][128 * 1280];
__device__ unsigned short g_Ulo[3][128 * 1280];

// ---------------- helpers ----------------
__device__ __forceinline__ uint32_t smem_u32(const void* p) {
    uint32_t a;
    asm("{ .reg .u64 t; cvta.to.shared.u64 t, %1; cvt.u32.u64 %0, t; }"
        : "=r"(a) : "l"(p));
    return a;
}
__device__ __forceinline__ void ldsm4(uint32_t* r, uint32_t addr) {
    asm volatile("ldmatrix.sync.aligned.m8n8.x4.shared.b16 {%0,%1,%2,%3}, [%4];"
                 : "=r"(r[0]), "=r"(r[1]), "=r"(r[2]), "=r"(r[3]) : "r"(addr));
}
__device__ __forceinline__ void mma16816(float* c, const uint32_t* a,
                                         uint32_t b0, uint32_t b1) {
    asm volatile("mma.sync.aligned.m16n8k16.row.col.f32.bf16.bf16.f32 "
                 "{%0,%1,%2,%3}, {%4,%5,%6,%7}, {%8,%9}, {%0,%1,%2,%3};"
                 : "+f"(c[0]), "+f"(c[1]), "+f"(c[2]), "+f"(c[3])
                 : "r"(a[0]), "r"(a[1]), "r"(a[2]), "r"(a[3]), "r"(b0), "r"(b1));
}
__device__ __forceinline__ void cp_async16(uint32_t daddr, const void* gptr) {
    asm volatile("cp.async.cg.shared.global [%0], [%1], 16;"
                 :: "r"(daddr), "l"(gptr));
}
#define CP_COMMIT() asm volatile("cp.async.commit_group;" ::: "memory")
#define CP_WAIT1()  asm volatile("cp.async.wait_group 1;" ::: "memory")
#define CP_WAIT0()  asm volatile("cp.async.wait_group 0;" ::: "memory")

// 16 fp32 -> bf16 hi/lo (scaled), packed as 2+2 uint4
__device__ __forceinline__ void conv16(const float4* f, float s, uint4* Hv, uint4* Lv) {
    uint32_t hw[8], lw[8];
    #pragma unroll
    for (int q = 0; q < 4; q++) {
        float v[4] = {f[q].x * s, f[q].y * s, f[q].z * s, f[q].w * s};
        uint16_t hb[4], lb[4];
        #pragma unroll
        for (int i = 0; i < 4; i++) {
            __nv_bfloat16 h = __float2bfloat16(v[i]);
            float hf        = __bfloat162float(h);
            __nv_bfloat16 l = __float2bfloat16(v[i] - hf);
            hb[i] = __bfloat16_as_ushort(h);
            lb[i] = __bfloat16_as_ushort(l);
        }
        hw[q * 2 + 0] = (uint32_t)hb[0] | ((uint32_t)hb[1] << 16);
        hw[q * 2 + 1] = (uint32_t)hb[2] | ((uint32_t)hb[3] << 16);
        lw[q * 2 + 0] = (uint32_t)lb[0] | ((uint32_t)lb[1] << 16);
        lw[q * 2 + 1] = (uint32_t)lb[2] | ((uint32_t)lb[3] << 16);
    }
    Hv[0] = make_uint4(hw[0], hw[1], hw[2], hw[3]);
    Hv[1] = make_uint4(hw[4], hw[5], hw[6], hw[7]);
    Lv[0] = make_uint4(lw[0], lw[1], lw[2], lw[3]);
    Lv[1] = make_uint4(lw[4], lw[5], lw[6], lw[7]);
}

// ---------------- index-width detection ----------------
__global__ void detect_kernel(const void* dst, int e, int n) {
    __shared__ int bad;
    if (threadIdx.x == 0) bad = 0;
    __syncthreads();
    int k = e < 1024 ? e : 1024;
    const long long* p = (const long long*)dst;
    for (int i = threadIdx.x; i < k; i += blockDim.x) {
        long long v = p[i];
        if (v < 0 || v >= (long long)n) atomicExch(&bad, 1);
    }
    __syncthreads();
    if (threadIdx.x == 0) g_is64 = bad ? 0 : 1;
}
__device__ __forceinline__ int load_idx(const void* p, int i) {
    if (g_is64) return (int)((const long long*)p)[i];
    return ((const int*)p)[i];
}

// ---------------- CSR build ----------------
__global__ void zero_deg(int n) {
    int i = blockIdx.x * blockDim.x + threadIdx.x;
    if (i < n) g_deg[i] = 0;
}
__global__ void hist_kernel(const void* __restrict__ dst, int e) {
    int i = blockIdx.x * blockDim.x + threadIdx.x;
    if (i < e) atomicAdd(&g_deg[load_idx(dst, i)], 1);
}

// ---- parallel scan: p1 block sums, p2 scan of block sums, p3 finalize ----
__global__ void scan_p1(int n) {
    int base = blockIdx.x * 1024 + threadIdx.x * 4;
    int s = 0;
    #pragma unroll
    for (int j = 0; j < 4; j++) {
        int i = base + j;
        if (i < n) s += g_deg[i];
    }
    #pragma unroll
    for (int o = 16; o; o >>= 1) s += __shfl_down_sync(0xFFFFFFFFu, s, o);
    __shared__ int ws[8];
    if ((threadIdx.x & 31) == 0) ws[threadIdx.x >> 5] = s;
    __syncthreads();
    if (threadIdx.x == 0) {
        int t = 0;
        #pragma unroll
        for (int w = 0; w < 8; w++) t += ws[w];
        g_bsum[blockIdx.x] = t;
    }
}
__global__ void scan_p2(int nb, int n) {
    int tid = threadIdx.x;
    int v = tid < nb ? g_bsum[tid] : 0;
    __shared__ int tmp[64];
    tmp[tid] = v;
    __syncthreads();
    #pragma unroll
    for (int o = 1; o < 64; o <<= 1) {
        int t = tid >= o ? tmp[tid - o] : 0;
        __syncthreads();
        tmp[tid] += t;
        __syncthreads();
    }
    if (tid < nb) g_bsum[tid] = tmp[tid] - v;
    if (tid == 0) g_off[n] = tmp[63];
}
__global__ void scan_p3(int n) {
    int tid  = threadIdx.x;
    int base = blockIdx.x * 1024 + tid * 4;
    int d[4], s = 0;
    #pragma unroll
    for (int j = 0; j < 4; j++) {
        int i = base + j;
        d[j] = (i < n) ? g_deg[i] : 0;
        s += d[j];
    }
    int lane = tid & 31, w = tid >> 5;
    int incl = s;
    #pragma unroll
    for (int o = 1; o < 32; o <<= 1) {
        int t = __shfl_up_sync(0xFFFFFFFFu, incl, o);
        if (lane >= o) incl += t;
    }
    __shared__ int ws[8];
    if (lane == 31) ws[w] = incl;
    __syncthreads();
    if (tid == 0) {
        int acc = 0;
        #pragma unroll
        for (int q = 0; q < 8; q++) { int t = ws[q]; ws[q] = acc; acc += t; }
    }
    __syncthreads();
    int run = incl - s + ws[w] + g_bsum[blockIdx.x];
    #pragma unroll
    for (int j = 0; j < 4; j++) {
        int i = base + j;
        if (i < n) {
            g_off[i] = run;
            g_cur[i] = run;
            float ld = logf((float)d[j] + 1.0f);
            g_amp[i] = ld * (1.0f / 3.0f);
            g_att[i] = 3.0f / fmaxf(ld, 1e-6f);
            run += d[j];
        }
    }
}

__global__ void scatter_kernel(const void* __restrict__ src,
                               const void* __restrict__ dst, int e) {
    int i = blockIdx.x * blockDim.x + threadIdx.x;
    if (i < e) {
        int d   = load_idx(dst, i);
        int pos = atomicAdd(&g_cur[d], 1);
        g_csr[pos] = load_idx(src, i);
    }
}

// ---------------- weight prepack (per-layer buffers) ----------------
template <int L>
__global__ void prepack_upd2(const float* __restrict__ Uw, int N) {
    int idx = blockIdx.x * blockDim.x + threadIdx.x;
    if (idx >= 1280 * N) return;
    int k = idx / N, n = idx % N;
    float v = Uw[idx];
    __nv_bfloat16 h = __float2bfloat16(v);
    float hf        = __bfloat162float(h);
    __nv_bfloat16 l = __float2bfloat16(v - hf);
    size_t pos = (size_t)n * 1280 + k;
    g_Uhi[L][pos] = __bfloat16_as_ushort(h);
    g_Ulo[L][pos] = __bfloat16_as_ushort(l);
}
template <int L>
__global__ void prepack_pq2(const float* __restrict__ Mw) {
    int idx = blockIdx.x * blockDim.x + threadIdx.x;
    if (idx >= 256 * 128) return;
    int n = idx >> 7, k = idx & 127;
    int mat = n >> 7, nn = n & 127;
    float v = Mw[(mat * 128 + k) * 128 + nn];
    __nv_bfloat16 h = __float2bfloat16(v);
    float hf        = __bfloat162float(h);
    __nv_bfloat16 l = __float2bfloat16(v - hf);
    size_t pos = (size_t)n * 128 + k;
    g_PQhi[L][pos] = __bfloat16_as_ushort(h);
    g_PQlo[L][pos] = __bfloat16_as_ushort(l);
}

// ---------------- input selection helper ----------------
template <int SEL>
__device__ __forceinline__ const float* sel_in(const float* a) {
    if constexpr (SEL == 1) return g_h1;
    else if constexpr (SEL == 2) return g_h2;
    else return a;
}

// ---------------- mma.sync update GEMM, cp.async B + A-prefetch pipeline ------
template <int INSEL, int OUTSEL, int BN, bool RELU, int L>
__global__ __launch_bounds__(256, 2) void mma_update(const float* __restrict__ hin,
                                                     const float* __restrict__ Ub,
                                                     float* __restrict__ outp, int M) {
    constexpr int KTOT = 1280, NCH = 40, WNT = BN / 16;
    constexpr int SB_STAGE = 2 * BN * 40;
    extern __shared__ __align__(16) char dyn[];
    uint16_t* sA = (uint16_t*)dyn;            // [2][128][40]
    uint16_t* sB = (uint16_t*)(dyn + 20480);  // [2 stages][2 imgs][BN][40]
    const float* H = sel_in<INSEL>(hin);
    float* C;
    if constexpr (OUTSEL == 1) C = g_h1;
    else if constexpr (OUTSEL == 2) C = g_h2;
    else C = outp;

    int tid = threadIdx.x, lane = tid & 31, wid = tid >> 5;
    int wm = wid & 3, wn = wid >> 2;
    int row0  = blockIdx.x * 128;
    int arow  = tid >> 1, ahalf = (tid & 1) * 16;
    int gr_a  = row0 + arow;
    bool va   = gr_a < M;
    float s_amp = va ? g_amp[gr_a] : 0.f;
    float s_att = va ? g_att[gr_a] : 0.f;

    float acc[2][WNT][4];
    #pragma unroll
    for (int mt = 0; mt < 2; mt++)
        #pragma unroll
        for (int t = 0; t < WNT; t++)
            #pragma unroll
            for (int j = 0; j < 4; j++) acc[mt][t][j] = 0.f;

    uint32_t a_base = smem_u32(sA);
    uint32_t b_base = smem_u32(sB);
    int lrow = lane & 15, lcol = (lane >> 4) * 8;

    auto aptr = [&](int k0) -> const float* {
        if (k0 < 128)      return H + (size_t)gr_a * 128 + k0;
        else if (k0 < 512) return g_agg + (size_t)gr_a * 384 + (k0 - 128);
        else if (k0 < 896) return g_agg + (size_t)gr_a * 384 + (k0 - 512);
        else               return g_agg + (size_t)gr_a * 384 + (k0 - 896);
    };
    auto ascale = [&](int k0) -> float {
        if (k0 < 512) return 1.f;
        else if (k0 < 896) return s_amp;
        else return s_att;
    };
    auto fillB = [&](int k0, int st) {
        uint32_t sbase = b_base + (uint32_t)(st * SB_STAGE * 2);
        #pragma unroll
        for (int i = tid; i < BN * 8; i += 256) {
            int img = i >= BN * 4;
            int j   = img ? i - BN * 4 : i;
            int n   = j >> 2, q = j & 3;
            const unsigned short* g = img ? g_Ulo[L] : g_Uhi[L];
            uint32_t daddr = sbase + (uint32_t)(((img * BN + n) * 40 + q * 8) * 2);
            cp_async16(daddr, g + (size_t)n * KTOT + k0 + q * 8);
        }
        CP_COMMIT();
    };

    // prologue: B stage 0 + A regs for chunk 0
    fillB(0, 0);
    float4 f[4];
    {
        const float* bp = aptr(0);
        #pragma unroll
        for (int q = 0; q < 4; q++)
            f[q] = va ? *(const float4*)(bp + ahalf + q * 4)
                      : make_float4(0.f, 0.f, 0.f, 0.f);
    }

    for (int kt = 0; kt < NCH; kt++) {
        int k0 = kt * 32;
        // ---- convert + store prefetched A
        uint4 Hv[2], Lv[2];
        conv16(f, ascale(k0), Hv, Lv);
        *(uint4*)&sA[(size_t)arow * 40 + ahalf]              = Hv[0];
        *(uint4*)&sA[(size_t)arow * 40 + ahalf + 8]          = Hv[1];
        *(uint4*)&sA[(size_t)(128 + arow) * 40 + ahalf]      = Lv[0];
        *(uint4*)&sA[(size_t)(128 + arow) * 40 + ahalf + 8]  = Lv[1];
        // ---- prefetch next B stage, wait for current
        if (kt + 1 < NCH) { fillB(k0 + 32, (kt + 1) & 1); CP_WAIT1(); }
        else              { CP_WAIT0(); }
        __syncthreads();
        // ---- prefetch next-chunk A (LDG latency hides under MMA below)
        if (kt + 1 < NCH) {
            const float* bp = aptr(k0 + 32);
            #pragma unroll
            for (int q = 0; q < 4; q++)
                f[q] = va ? *(const float4*)(bp + ahalf + q * 4)
                          : make_float4(0.f, 0.f, 0.f, 0.f);
        }
        // ---- mma on stage kt&1
        uint32_t bst = b_base + (uint32_t)((kt & 1) * SB_STAGE * 2);
        #pragma unroll
        for (int ks = 0; ks < 2; ks++) {
            uint32_t ah[2][4], al[2][4];
            #pragma unroll
            for (int mt = 0; mt < 2; mt++) {
                uint32_t r = a_base + (uint32_t)(((wm * 32 + mt * 16 + lrow) * 40 + ks * 16 + lcol) * 2);
                ldsm4(ah[mt], r);
                ldsm4(al[mt], r + 128 * 40 * 2);
            }
            uint32_t bf[WNT / 2][4];
            #pragma unroll
            for (int pt = 0; pt < WNT / 2; pt++) {
                uint32_t r = bst + (uint32_t)(((wn * (BN / 2) + pt * 16 + lrow) * 40 + ks * 16 + lcol) * 2);
                ldsm4(bf[pt], r);
            }
            #pragma unroll
            for (int mt = 0; mt < 2; mt++)
                #pragma unroll
                for (int t = 0; t < WNT; t++) {
                    uint32_t b0 = bf[t >> 1][t & 1], b1 = bf[t >> 1][2 + (t & 1)];
                    mma16816(acc[mt][t], ah[mt], b0, b1);
                    mma16816(acc[mt][t], al[mt], b0, b1);
                }
            #pragma unroll
            for (int pt = 0; pt < WNT / 2; pt++) {
                uint32_t r = bst + (uint32_t)(BN * 40 * 2) +
                             (uint32_t)(((wn * (BN / 2) + pt * 16 + lrow) * 40 + ks * 16 + lcol) * 2);
                ldsm4(bf[pt], r);
            }
            #pragma unroll
            for (int mt = 0; mt < 2; mt++)
                #pragma unroll
                for (int t = 0; t < WNT; t++) {
                    uint32_t b0 = bf[t >> 1][t & 1], b1 = bf[t >> 1][2 + (t & 1)];
                    mma16816(acc[mt][t], ah[mt], b0, b1);
                }
        }
        __syncthreads();
    }
    // ---- epilogue
    int gq = lane >> 2, tg = lane & 3;
    #pragma unroll
    for (int mt = 0; mt < 2; mt++) {
        #pragma unroll
        for (int t = 0; t < WNT; t++) {
            int col = wn * (BN / 2) + t * 8 + tg * 2;
            float u0 = Ub[col], u1 = Ub[col + 1];
            int r0 = row0 + wm * 32 + mt * 16 + gq;
            float v0 = acc[mt][t][0] + u0, v1 = acc[mt][t][1] + u1;
            float v2 = acc[mt][t][2] + u0, v3 = acc[mt][t][3] + u1;
            if (RELU) {
                v0 = fmaxf(v0, 0.f); v1 = fmaxf(v1, 0.f);
                v2 = fmaxf(v2, 0.f); v3 = fmaxf(v3, 0.f);
            }
            if (r0 < M)     *(float2*)&C[(size_t)r0 * BN + col]       = make_float2(v0, v1);
            if (r0 + 8 < M) *(float2*)&C[(size_t)(r0 + 8) * BN + col] = make_float2(v2, v3);
        }
    }
}

// ---------------- mma.sync PQ GEMM: grid.y=0 -> P, 1 -> Q(+Mb) ----------------
template <int INSEL, int L>
__global__ __launch_bounds__(256, 2) void mma_pq(const float* __restrict__ hin,
                                                 const float* __restrict__ Mb, int M) {
    constexpr int KTOT = 128, NCH = 4, BN = 128, WNT = 8;
    __shared__ __align__(16) uint16_t sA[2][128][40];
    __shared__ __align__(16) uint16_t sB[2][BN][40];
    const float* H = sel_in<INSEL>(hin);
    int mat = blockIdx.y;
    float* C = mat ? g_Q : g_P;

    int tid = threadIdx.x, lane = tid & 31, wid = tid >> 5;
    int wm = wid & 3, wn = wid >> 2;
    int row0  = blockIdx.x * 128;
    int arow  = tid >> 1, ahalf = (tid & 1) * 16;
    int gr_a  = row0 + arow;
    bool va   = gr_a < M;

    float acc[2][WNT][4];
    #pragma unroll
    for (int mt = 0; mt < 2; mt++)
        #pragma unroll
        for (int t = 0; t < WNT; t++)
            #pragma unroll
            for (int j = 0; j < 4; j++) acc[mt][t][j] = 0.f;

    uint32_t a_base = smem_u32(&sA[0][0][0]);
    uint32_t b_base = smem_u32(&sB[0][0][0]);
    int lrow = lane & 15, lcol = (lane >> 4) * 8;

    for (int kt = 0; kt < NCH; kt++) {
        int k0 = kt * 32;
        const float* bp = H + (size_t)gr_a * 128 + k0;
        float4 f[4];
        #pragma unroll
        for (int q = 0; q < 4; q++)
            f[q] = va ? *(const float4*)(bp + ahalf + q * 4)
                      : make_float4(0.f, 0.f, 0.f, 0.f);
        uint4 Hv[2], Lv[2];
        conv16(f, 1.0f, Hv, Lv);
        *(uint4*)&sA[0][arow][ahalf]     = Hv[0];
        *(uint4*)&sA[0][arow][ahalf + 8] = Hv[1];
        *(uint4*)&sA[1][arow][ahalf]     = Lv[0];
        *(uint4*)&sA[1][arow][ahalf + 8] = Lv[1];
        #pragma unroll
        for (int i = tid; i < BN * 8; i += 256) {
            int img = i >= BN * 4;
            int j   = img ? i - BN * 4 : i;
            int n   = j >> 2, q = j & 3;
            const unsigned short* g = img ? g_PQlo[L] : g_PQhi[L];
            uint4 v = *(const uint4*)(g + (size_t)(mat * 128 + n) * KTOT + k0 + q * 8);
            *(uint4*)&sB[img][n][q * 8] = v;
        }
        __syncthreads();
        #pragma unroll
        for (int ks = 0; ks < 2; ks++) {
            uint32_t ah[2][4], al[2][4];
            #pragma unroll
            for (int mt = 0; mt < 2; mt++) {
                uint32_t r = a_base + (uint32_t)(((wm * 32 + mt * 16 + lrow) * 40 + ks * 16 + lcol) * 2);
                ldsm4(ah[mt], r);
                ldsm4(al[mt], r + 128 * 40 * 2);
            }
            uint32_t bf[WNT / 2][4];
            #pragma unroll
            for (int pt = 0; pt < WNT / 2; pt++) {
                uint32_t r = b_base + (uint32_t)(((wn * 64 + pt * 16 + lrow) * 40 + ks * 16 + lcol) * 2);
                ldsm4(bf[pt], r);
            }
            #pragma unroll
            for (int mt = 0; mt < 2; mt++)
                #pragma unroll
                for (int t = 0; t < WNT; t++) {
                    uint32_t b0 = bf[t >> 1][t & 1], b1 = bf[t >> 1][2 + (t & 1)];
                    mma16816(acc[mt][t], ah[mt], b0, b1);
                    mma16816(acc[mt][t], al[mt], b0, b1);
                }
            #pragma unroll
            for (int pt = 0; pt < WNT / 2; pt++) {
                uint32_t r = b_base + BN * 40 * 2 +
                             (uint32_t)(((wn * 64 + pt * 16 + lrow) * 40 + ks * 16 + lcol) * 2);
                ldsm4(bf[pt], r);
            }
            #pragma unroll
            for (int mt = 0; mt < 2; mt++)
                #pragma unroll
                for (int t = 0; t < WNT; t++) {
                    uint32_t b0 = bf[t >> 1][t & 1], b1 = bf[t >> 1][2 + (t & 1)];
                    mma16816(acc[mt][t], ah[mt], b0, b1);
                }
        }
        __syncthreads();
    }
    int gq = lane >> 2, tg = lane & 3;
    #pragma unroll
    for (int mt = 0; mt < 2; mt++) {
        #pragma unroll
        for (int t = 0; t < WNT; t++) {
            int col = wn * 64 + t * 8 + tg * 2;
            float u0 = mat ? Mb[col] : 0.f;
            float u1 = mat ? Mb[col + 1] : 0.f;
            int r0 = row0 + wm * 32 + mt * 16 + gq;
            if (r0 < M)
                *(float2*)&C[(size_t)r0 * 128 + col] =
                    make_float2(acc[mt][t][0] + u0, acc[mt][t][1] + u1);
            if (r0 + 8 < M)
                *(float2*)&C[(size_t)(r0 + 8) * 128 + col] =
                    make_float2(acc[mt][t][2] + u0, acc[mt][t][3] + u1);
        }
    }
}

// ---------------- CSR aggregation: warp per node, float4 per lane ----------------
__global__ void agg_kernel(int n) {
    int gw   = (blockIdx.x * blockDim.x + threadIdx.x) >> 5;
    int lane = threadIdx.x & 31;
    if (gw >= n) return;
    int s = g_off[gw], e = g_off[gw + 1];
    int c = lane * 4;
    float4 sum = make_float4(0.f, 0.f, 0.f, 0.f);
    float4 mn  = make_float4(1e30f, 1e30f, 1e30f, 1e30f);
    float4 mx  = make_float4(-1e30f, -1e30f, -1e30f, -1e30f);
    for (int i = s; i < e; i++) {
        int r    = g_csr[i];
        float4 v = *(const float4*)&g_P[(size_t)r * 128 + c];
        sum.x += v.x; sum.y += v.y; sum.z += v.z; sum.w += v.w;
        mn.x = fminf(mn.x, v.x); mn.y = fminf(mn.y, v.y);
        mn.z = fminf(mn.z, v.z); mn.w = fminf(mn.w, v.w);
        mx.x = fmaxf(mx.x, v.x); mx.y = fmaxf(mx.y, v.y);
        mx.z = fmaxf(mx.z, v.z); mx.w = fmaxf(mx.w, v.w);
    }
    float4 q = *(const float4*)&g_Q[(size_t)gw * 128 + c];
    float4 me, on, ox;
    int d = e - s;
    if (d > 0) {
        float inv = 1.0f / (float)d;
        me.x = sum.x * inv + q.x; me.y = sum.y * inv + q.y;
        me.z = sum.z * inv + q.z; me.w = sum.w * inv + q.w;
        on.x = mn.x + q.x; on.y = mn.y + q.y; on.z = mn.z + q.z; on.w = mn.w + q.w;
        ox.x = mx.x + q.x; ox.y = mx.y + q.y; ox.z = mx.z + q.z; ox.w = mx.w + q.w;
    } else {
        me = make_float4(0.f, 0.f, 0.f, 0.f);
        on = me; ox = me;
    }
    *(float4*)&g_agg[(size_t)gw * 384 + c]       = me;
    *(float4*)&g_agg[(size_t)gw * 384 + 128 + c] = on;
    *(float4*)&g_agg[(size_t)gw * 384 + 256 + c] = ox;
}

// ---------------- host launcher ----------------
extern "C" void kernel_launch(void* const* d_in, const int* in_sizes, int n_in,
                              void* d_out, int out_size) {
    const float* x   = (const float*)d_in[0];
    const void*  src = d_in[1];
    const void*  dst = d_in[2];
    const float* M0w = (const float*)d_in[3];
    const float* M0b = (const float*)d_in[4];
    const float* U0w = (const float*)d_in[5];
    const float* U0b = (const float*)d_in[6];
    const float* M1w = (const float*)d_in[7];
    const float* M1b = (const float*)d_in[8];
    const float* U1w = (const float*)d_in[9];
    const float* U1b = (const float*)d_in[10];
    const float* M2w = (const float*)d_in[11];
    const float* M2b = (const float*)d_in[12];
    const float* U2w = (const float*)d_in[13];
    const float* U2b = (const float*)d_in[14];

    int n = in_sizes[0] / 128;
    int e = in_sizes[1];
    if (n > NN) n = NN;
    if (e > NE) e = NE;

    // one-time side streams + events (created on first, uncaptured, call)
    static cudaStream_t s1 = nullptr, s2 = nullptr;
    static cudaEvent_t evStart1 = nullptr, evStart2 = nullptr, evCSR = nullptr, evPre = nullptr;
    if (s1 == nullptr) {
        cudaStreamCreateWithFlags(&s1, cudaStreamNonBlocking);
        cudaStreamCreateWithFlags(&s2, cudaStreamNonBlocking);
        cudaEventCreateWithFlags(&evStart1, cudaEventDisableTiming);
        cudaEventCreateWithFlags(&evStart2, cudaEventDisableTiming);
        cudaEventCreateWithFlags(&evCSR, cudaEventDisableTiming);
        cudaEventCreateWithFlags(&evPre, cudaEventDisableTiming);
    }

    const int UPD_SMEM_H = 20480 + 2 * 2 * 128 * 40 * 2;  // 61440 (BN=128)
    const int UPD_SMEM_L = 20480 + 2 * 2 * 64 * 40 * 2;   // 40960 (BN=64)
    cudaFuncSetAttribute(mma_update<0, 1, 128, true, 0>,
                         cudaFuncAttributeMaxDynamicSharedMemorySize, UPD_SMEM_H);
    cudaFuncSetAttribute(mma_update<1, 2, 128, true, 1>,
                         cudaFuncAttributeMaxDynamicSharedMemorySize, UPD_SMEM_H);
    cudaFuncSetAttribute(mma_update<2, 0, 64, false, 2>,
                         cudaFuncAttributeMaxDynamicSharedMemorySize, UPD_SMEM_L);

    int gE = (e + 255) / 256;
    int gN = (n + 255) / 256;
    int gM = (n + 127) / 128;
    int gA = (n * 32 + 255) / 256;
    int nb = (n + 1023) / 1024;

    // fork: s1 = CSR build, s2 = remaining prepacks; main starts layer-0 PQ
    cudaEventRecord(evStart1, 0);
    cudaStreamWaitEvent(s1, evStart1, 0);
    cudaEventRecord(evStart2, 0);
    cudaStreamWaitEvent(s2, evStart2, 0);

    // s1: CSR build + node scalars
    detect_kernel<<<1, 256, 0, s1>>>(dst, e, n);
    zero_deg<<<gN, 256, 0, s1>>>(n);
    hist_kernel<<<gE, 256, 0, s1>>>(dst, e);
    scan_p1<<<nb, 256, 0, s1>>>(n);
    scan_p2<<<1, 64, 0, s1>>>(nb, n);
    scan_p3<<<nb, 256, 0, s1>>>(n);
    scatter_kernel<<<gE, 256, 0, s1>>>(src, dst, e);
    cudaEventRecord(evCSR, s1);

    // s2: all update prepacks + later-layer PQ prepacks
    prepack_upd2<0><<<(1280 * 128 + 255) / 256, 256, 0, s2>>>(U0w, 128);
    prepack_upd2<1><<<(1280 * 128 + 255) / 256, 256, 0, s2>>>(U1w, 128);
    prepack_upd2<2><<<(1280 * 64 + 255) / 256, 256, 0, s2>>>(U2w, 64);
    prepack_pq2<1><<<128, 256, 0, s2>>>(M1w);
    prepack_pq2<2><<<128, 256, 0, s2>>>(M2w);
    cudaEventRecord(evPre, s2);

    // main: layer 0 PQ (needs only its own prepack)
    prepack_pq2<0><<<128, 256>>>(M0w);
    mma_pq<0, 0><<<dim3(gM, 2), 256>>>(x, M0b, n);
    cudaStreamWaitEvent(0, evCSR, 0);   // agg needs CSR
    agg_kernel<<<gA, 256>>>(n);
    cudaStreamWaitEvent(0, evPre, 0);   // update needs its prepack
    mma_update<0, 1, 128, true, 0><<<gM, 256, UPD_SMEM_H>>>(x, U0b, nullptr, n);

    // layer 1
    mma_pq<1, 1><<<dim3(gM, 2), 256>>>(nullptr, M1b, n);
    agg_kernel<<<gA, 256>>>(n);
    mma_update<1, 2, 128, true, 1><<<gM, 256, UPD_SMEM_H>>>(nullptr, U1b, nullptr, n);

    // layer 2 (N=64, no relu)
    mma_pq<2, 2><<<dim3(gM, 2), 256>>>(nullptr, M2b, n);
    agg_kernel<<<gA, 256>>>(n);
    mma_update<2, 0, 64, false, 2><<<gM, 256, UPD_SMEM_L>>>(nullptr, U2b, (float*)d_out, n);
}